// round 4
// baseline (speedup 1.0000x reference)
#include <cuda_runtime.h>
#include <cuda_fp16.h>
#include <math.h>
#include <stdint.h>

// Problem constants
#define BB 2
#define NN 384
#define DD 128
#define VV 8192
#define LL 2
#define NPAIR_B 73920
#define NPAIR_T 147840
#define PT 128
#define NTILES_MMA 1155      // 147840 / 128
#define PGRID 148

// ---------------- scratch ----------------
__device__ float g_x[BB * NN * DD];
__device__ float g_a[BB * NN * 256];
__device__ float g_c[BB * NN * 256];
__device__ float g_h[BB * NN * 512];
__device__ float g_y[BB * NN * DD];
__device__ float g_p[(size_t)BB * NN * NN * DD];
__device__ float g_s[BB * NN * NN];

// exact gelu via A&S 7.1.26 erf (max abs err 1.5e-7)
__device__ __forceinline__ float gelu_fast(float x) {
    float y = fabsf(x) * 0.70710678118654752f;
    float q = fmaf(0.3275911f, y, 1.0f);
    float t;
    asm("rcp.approx.f32 %0, %1;" : "=f"(t) : "f"(q));
    float p = fmaf(fmaf(fmaf(fmaf(1.061405429f, t, -1.453152027f), t,
                             1.421413741f), t, -0.284496736f), t, 0.254829592f) * t;
    float e = __expf(-y * y);
    float erf_abs = fmaf(-p, e, 1.0f);
    float s = copysignf(erf_abs, x);
    return 0.5f * x * (1.0f + s);
}

__device__ __forceinline__ void ldsm4(uint32_t* r, uint32_t addr) {
    asm volatile("ldmatrix.sync.aligned.m8n8.x4.shared.b16 {%0,%1,%2,%3}, [%4];"
                 : "=r"(r[0]), "=r"(r[1]), "=r"(r[2]), "=r"(r[3]) : "r"(addr));
}
__device__ __forceinline__ void ldsm4t(uint32_t* r, uint32_t addr) {
    asm volatile("ldmatrix.sync.aligned.m8n8.x4.trans.shared.b16 {%0,%1,%2,%3}, [%4];"
                 : "=r"(r[0]), "=r"(r[1]), "=r"(r[2]), "=r"(r[3]) : "r"(addr));
}
__device__ __forceinline__ void mma_f16(float c[4], const uint32_t a[4],
                                        uint32_t b0, uint32_t b1) {
    asm volatile(
        "mma.sync.aligned.m16n8k16.row.col.f32.f16.f16.f32 "
        "{%0,%1,%2,%3}, {%4,%5,%6,%7}, {%8,%9}, {%0,%1,%2,%3};"
        : "+f"(c[0]), "+f"(c[1]), "+f"(c[2]), "+f"(c[3])
        : "r"(a[0]), "r"(a[1]), "r"(a[2]), "r"(a[3]), "r"(b0), "r"(b1));
}

// ---------------- embedding ----------------
__global__ void embed_kernel(const int* __restrict__ ids,
                             const float* __restrict__ emb,
                             const float* __restrict__ pos) {
    int t = blockIdx.x * blockDim.x + threadIdx.x;
    if (t >= BB * NN * DD) return;
    int d = t & (DD - 1);
    int bn = t >> 7;
    int n = bn % NN;
    g_x[t] = emb[ids[bn] * DD + d] + pos[n * DD + d];
}

// ---------------- generic 64x64x16 fp32 GEMM ----------------
template <int ACT>
__global__ __launch_bounds__(256) void gemm64(
    const float* __restrict__ A, const float* __restrict__ W,
    const float* __restrict__ bias, float* __restrict__ C,
    int K, int ldA, int ldW, int ldC) {
    __shared__ float As[16][64];
    __shared__ float Ws[16][64];
    const int bm = blockIdx.y * 64;
    const int bn = blockIdx.x * 64;
    const int tid = threadIdx.x;

    const int ar = tid >> 2;
    const int ak = (tid & 3) * 4;
    const int wk = tid >> 4;
    const int wn = (tid & 15) * 4;
    const int tm = (tid >> 4) * 4;
    const int tn = (tid & 15) * 4;

    float acc[4][4] = {};
    for (int k0 = 0; k0 < K; k0 += 16) {
        float4 av = *(const float4*)&A[(size_t)(bm + ar) * ldA + k0 + ak];
        As[ak + 0][ar] = av.x;
        As[ak + 1][ar] = av.y;
        As[ak + 2][ar] = av.z;
        As[ak + 3][ar] = av.w;
        *(float4*)&Ws[wk][wn] = *(const float4*)&W[(size_t)(k0 + wk) * ldW + bn + wn];
        __syncthreads();
#pragma unroll
        for (int k = 0; k < 16; k++) {
            float4 a = *(const float4*)&As[k][tm];
            float4 w = *(const float4*)&Ws[k][tn];
            acc[0][0] += a.x * w.x; acc[0][1] += a.x * w.y; acc[0][2] += a.x * w.z; acc[0][3] += a.x * w.w;
            acc[1][0] += a.y * w.x; acc[1][1] += a.y * w.y; acc[1][2] += a.y * w.z; acc[1][3] += a.y * w.w;
            acc[2][0] += a.z * w.x; acc[2][1] += a.z * w.y; acc[2][2] += a.z * w.z; acc[2][3] += a.z * w.w;
            acc[3][0] += a.w * w.x; acc[3][1] += a.w * w.y; acc[3][2] += a.w * w.z; acc[3][3] += a.w * w.w;
        }
        __syncthreads();
    }
    float4 bv = make_float4(0.f, 0.f, 0.f, 0.f);
    if (bias) bv = *(const float4*)&bias[bn + tn];
#pragma unroll
    for (int r = 0; r < 4; r++) {
        float4 o;
        o.x = acc[r][0] + bv.x;
        o.y = acc[r][1] + bv.y;
        o.z = acc[r][2] + bv.z;
        o.w = acc[r][3] + bv.w;
        if (ACT == 1) {
            o.x = gelu_fast(o.x); o.y = gelu_fast(o.y);
            o.z = gelu_fast(o.z); o.w = gelu_fast(o.w);
        }
        *(float4*)&C[(size_t)(bm + tm + r) * ldC + bn + tn] = o;
    }
}

// ---------------- pair kernel: persistent, W-resident, fp16 mma ------------
// Strides (halves): row-addr mod 8 (16B units) == 1 -> conflict-free ldmatrix
#define SA 264    // H1 [128][256]+8 pad
#define SBW 136   // W2 [256][128]+8, W3 [128][128]+8
#define SH 136    // H2 [128][128]+8
#define SPF 132   // Pf fp32 [128][128]+4
// byte offsets
#define OW2 0
#define OW3 69632
#define OH1 104448
#define OH2 172032
#define OB2 206848
#define OB3 207360
#define ORA 207872
#define ORC 208384
#define OPO 208896
#define PM_SMEM_BYTES 209408

__global__ __launch_bounds__(512, 1) void pair_mma(
    const float* __restrict__ W2, const float* __restrict__ b2,
    const float* __restrict__ W3, const float* __restrict__ b3) {
    extern __shared__ char smc[];
    __half* W2s = (__half*)(smc + OW2);
    __half* W3s = (__half*)(smc + OW3);
    __half* H1s = (__half*)(smc + OH1);
    __half* H2s = (__half*)(smc + OH2);
    float* Pf = (float*)(smc + OH1);      // epilogue-2 staging (overlaps H1)
    float* b2s = (float*)(smc + OB2);
    float* b3s = (float*)(smc + OB3);
    int* rowA = (int*)(smc + ORA);
    int* rowC = (int*)(smc + ORC);
    int* poff = (int*)(smc + OPO);

    const int tid = threadIdx.x;
    const int lane = tid & 31;
    const int warp = tid >> 5;
    const int wm = warp >> 2;     // 0..3 -> M base wm*32
    const int wn2 = warp & 3;     // 0..3 -> N base wn2*32
    const int lr = lane >> 2;
    const int lc = lane & 3;

    const int lrow = (lane & 7) + ((lane >> 3) & 1) * 8;
    const int lcol = (lane >> 4) * 8;

    const uint32_t sb = (uint32_t)__cvta_generic_to_shared(smc);
    const uint32_t h1_lane = sb + OH1 + (uint32_t)(lrow * SA + lcol) * 2;
    const uint32_t w2_lane = sb + OW2 + (uint32_t)(lrow * SBW + lcol) * 2;
    const uint32_t w3_lane = sb + OW3 + (uint32_t)(lrow * SBW + lcol) * 2;
    const uint32_t h2_lane = sb + OH2 + (uint32_t)(lrow * SH + lcol) * 2;

    // weights resident: convert once per CTA
    for (int e = tid; e < 256 * 32; e += 512) {
        int k = e >> 5, n4 = e & 31;
        const float4 wv = *(const float4*)&W2[(size_t)k * 128 + n4 * 4];
        __half2* d = (__half2*)(W2s + k * SBW + n4 * 4);
        d[0] = __floats2half2_rn(wv.x, wv.y);
        d[1] = __floats2half2_rn(wv.z, wv.w);
    }
    for (int e = tid; e < 128 * 32; e += 512) {
        int k = e >> 5, n4 = e & 31;
        const float4 wv = *(const float4*)&W3[(size_t)k * 128 + n4 * 4];
        __half2* d = (__half2*)(W3s + k * SBW + n4 * 4);
        d[0] = __floats2half2_rn(wv.x, wv.y);
        d[1] = __floats2half2_rn(wv.z, wv.w);
    }
    if (tid < 128) {
        b2s[tid] = b2[tid];
        b3s[tid] = b3[tid];
    }

    uint32_t af[2][4];
    uint32_t bf[4];

    for (int tile = blockIdx.x; tile < NTILES_MMA; tile += PGRID) {
        if (tid < 128) {
            int g = tile * PT + tid;
            int b = (g >= NPAIR_B) ? 1 : 0;
            int idx = g - b * NPAIR_B;
            int i = (int)((sqrtf(8.0f * (float)idx + 1.0f) - 1.0f) * 0.5f);
            while ((i + 1) * (i + 2) / 2 <= idx) ++i;
            while (i * (i + 1) / 2 > idx) --i;
            int j = idx - i * (i + 1) / 2;
            rowA[tid] = b * NN + i;
            rowC[tid] = b * NN + j;
            poff[tid] = (b * NN + i) * NN + j;
        }
        __syncthreads();   // weights+decode ready; prev writeout done

        // build full H1 [128][256] half
        for (int e = tid; e < 128 * 64; e += 512) {
            int r = e >> 6, c4 = e & 63;
            const float4 av = *(const float4*)&g_a[rowA[r] * 256 + c4 * 4];
            const float4 cv = *(const float4*)&g_c[rowC[r] * 256 + c4 * 4];
            __half2* d = (__half2*)(H1s + r * SA + c4 * 4);
            d[0] = __floats2half2_rn(gelu_fast(av.x + cv.x), gelu_fast(av.y + cv.y));
            d[1] = __floats2half2_rn(gelu_fast(av.z + cv.z), gelu_fast(av.w + cv.w));
        }
        __syncthreads();

        // ---------- GEMM1: K=256, 16 uninterrupted k-steps ----------
        float acc[2][4][4] = {};
#pragma unroll
        for (int ks = 0; ks < 16; ks++) {
            const int kb = ks * 16;
            ldsm4(af[0], h1_lane + (uint32_t)((wm * 32) * SA + kb) * 2);
            ldsm4(af[1], h1_lane + (uint32_t)((wm * 32 + 16) * SA + kb) * 2);
#pragma unroll
            for (int bt = 0; bt < 2; bt++) {
                ldsm4t(bf, w2_lane + (uint32_t)(kb * SBW + wn2 * 32 + bt * 16) * 2);
                mma_f16(acc[0][2 * bt], af[0], bf[0], bf[1]);
                mma_f16(acc[1][2 * bt], af[1], bf[0], bf[1]);
                mma_f16(acc[0][2 * bt + 1], af[0], bf[2], bf[3]);
                mma_f16(acc[1][2 * bt + 1], af[1], bf[2], bf[3]);
            }
        }
        // epilogue 1: +b2, gelu, half -> H2s
#pragma unroll
        for (int mt = 0; mt < 2; mt++) {
            int r0 = wm * 32 + mt * 16 + lr;
#pragma unroll
            for (int nf = 0; nf < 4; nf++) {
                int cb = wn2 * 32 + nf * 8 + 2 * lc;
                float bx = b2s[cb], by = b2s[cb + 1];
                *(__half2*)(H2s + r0 * SH + cb) =
                    __floats2half2_rn(gelu_fast(acc[mt][nf][0] + bx), gelu_fast(acc[mt][nf][1] + by));
                *(__half2*)(H2s + (r0 + 8) * SH + cb) =
                    __floats2half2_rn(gelu_fast(acc[mt][nf][2] + bx), gelu_fast(acc[mt][nf][3] + by));
            }
        }
        __syncthreads();

        // ---------- GEMM2: K=128, 8 k-steps ----------
        float acc2[2][4][4] = {};
#pragma unroll
        for (int ks = 0; ks < 8; ks++) {
            const int kb = ks * 16;
            ldsm4(af[0], h2_lane + (uint32_t)((wm * 32) * SH + kb) * 2);
            ldsm4(af[1], h2_lane + (uint32_t)((wm * 32 + 16) * SH + kb) * 2);
#pragma unroll
            for (int bt = 0; bt < 2; bt++) {
                ldsm4t(bf, w3_lane + (uint32_t)(kb * SBW + wn2 * 32 + bt * 16) * 2);
                mma_f16(acc2[0][2 * bt], af[0], bf[0], bf[1]);
                mma_f16(acc2[1][2 * bt], af[1], bf[0], bf[1]);
                mma_f16(acc2[0][2 * bt + 1], af[0], bf[2], bf[3]);
                mma_f16(acc2[1][2 * bt + 1], af[1], bf[2], bf[3]);
            }
        }
        // epilogue 2: +b3 -> Pf (overlaps dead H1)
#pragma unroll
        for (int mt = 0; mt < 2; mt++) {
            int r0 = wm * 32 + mt * 16 + lr;
#pragma unroll
            for (int nf = 0; nf < 4; nf++) {
                int cb = wn2 * 32 + nf * 8 + 2 * lc;
                float bx = b3s[cb], by = b3s[cb + 1];
                *(float2*)(Pf + r0 * SPF + cb) =
                    make_float2(acc2[mt][nf][0] + bx, acc2[mt][nf][1] + by);
                *(float2*)(Pf + (r0 + 8) * SPF + cb) =
                    make_float2(acc2[mt][nf][2] + bx, acc2[mt][nf][3] + by);
            }
        }
        __syncthreads();

        // writeout: 4 threads per pair-row (32 cols each) + norm
        {
            int r = tid >> 2, q = tid & 3;
            const float* src = Pf + r * SPF + q * 32;
            float* dst = g_p + (size_t)poff[r] * DD + q * 32;
            float ss = 0.f;
#pragma unroll
            for (int u = 0; u < 32; u += 4) {
                float4 v = *(const float4*)(src + u);
                *(float4*)(dst + u) = v;
                ss += v.x * v.x + v.y * v.y + v.z * v.z + v.w * v.w;
            }
            ss += __shfl_xor_sync(0xffffffffu, ss, 1);
            ss += __shfl_xor_sync(0xffffffffu, ss, 2);
            if (q == 0) g_s[poff[r]] = sqrtf(fmaxf(ss, 1e-30f));
        }
        __syncthreads();   // Pf/poff reuse protection
    }
}

// ---------------- head: fp16 mma, 128x128 tiles ----------------
#define OHX 0
#define OHW 34816
#define OHB 69632
#define HD_SMEM_BYTES 70144

__global__ __launch_bounds__(256) void head_mma(
    const float* __restrict__ headW, const float* __restrict__ headb,
    float* __restrict__ out) {
    extern __shared__ char smc[];
    __half* Xh = (__half*)(smc + OHX);
    __half* Wh = (__half*)(smc + OHW);
    float* biass = (float*)(smc + OHB);
    float* Pf = (float*)smc;             // output staging (overlaps Xh/Wh)

    const int tid = threadIdx.x;
    const int lane = tid & 31;
    const int warp = tid >> 5;
    const int wm = warp >> 1;
    const int wn = warp & 1;
    const int lr = lane >> 2;
    const int lc = lane & 3;
    const int lrow = (lane & 7) + ((lane >> 3) & 1) * 8;
    const int lcol = (lane >> 4) * 8;

    const int n0 = blockIdx.x * 128;
    const int m0 = blockIdx.y * 128;

    const uint32_t sb = (uint32_t)__cvta_generic_to_shared(smc);
    const uint32_t x_lane = sb + OHX + (uint32_t)(lrow * SBW + lcol) * 2;
    const uint32_t w_lane = sb + OHW + (uint32_t)(lrow * SBW + lcol) * 2;

    for (int e = tid; e < 128 * 32; e += 256) {
        int r = e >> 5, c4 = e & 31;
        const float4 v = *(const float4*)&g_x[(m0 + r) * DD + c4 * 4];
        __half2* d = (__half2*)(Xh + r * SBW + c4 * 4);
        d[0] = __floats2half2_rn(v.x, v.y);
        d[1] = __floats2half2_rn(v.z, v.w);
    }
    for (int e = tid; e < 128 * 32; e += 256) {
        int k = e >> 5, n4 = e & 31;
        const float4 v = *(const float4*)&headW[(size_t)k * VV + n0 + n4 * 4];
        __half2* d = (__half2*)(Wh + k * SBW + n4 * 4);
        d[0] = __floats2half2_rn(v.x, v.y);
        d[1] = __floats2half2_rn(v.z, v.w);
    }
    if (tid < 128) biass[tid] = headb[n0 + tid];
    __syncthreads();

    float acc[2][8][4] = {};
    uint32_t af[2][4];
    uint32_t bf[4];
#pragma unroll
    for (int ks = 0; ks < 8; ks++) {
        const int kb = ks * 16;
        ldsm4(af[0], x_lane + (uint32_t)((wm * 32) * SBW + kb) * 2);
        ldsm4(af[1], x_lane + (uint32_t)((wm * 32 + 16) * SBW + kb) * 2);
#pragma unroll
        for (int bt = 0; bt < 4; bt++) {
            ldsm4t(bf, w_lane + (uint32_t)(kb * SBW + wn * 64 + bt * 16) * 2);
            mma_f16(acc[0][2 * bt], af[0], bf[0], bf[1]);
            mma_f16(acc[1][2 * bt], af[1], bf[0], bf[1]);
            mma_f16(acc[0][2 * bt + 1], af[0], bf[2], bf[3]);
            mma_f16(acc[1][2 * bt + 1], af[1], bf[2], bf[3]);
        }
    }
    __syncthreads();   // all reads of Xh/Wh done before Pf overwrite

#pragma unroll
    for (int mt = 0; mt < 2; mt++) {
        int r0 = wm * 32 + mt * 16 + lr;
#pragma unroll
        for (int nt = 0; nt < 8; nt++) {
            int cb = wn * 64 + nt * 8 + 2 * lc;
            float bx = biass[cb], by = biass[cb + 1];
            *(float2*)(Pf + r0 * SPF + cb) =
                make_float2(acc[mt][nt][0] + bx, acc[mt][nt][1] + by);
            *(float2*)(Pf + (r0 + 8) * SPF + cb) =
                make_float2(acc[mt][nt][2] + bx, acc[mt][nt][3] + by);
        }
    }
    __syncthreads();

    // coalesced writeout: 2 threads per row
    {
        int r = tid >> 1, hf = tid & 1;
        const float* src = Pf + r * SPF + hf * 64;
        float* dst = out + (size_t)(m0 + r) * VV + n0 + hf * 64;
#pragma unroll
        for (int u = 0; u < 64; u += 4)
            *(float4*)(dst + u) = *(const float4*)(src + u);
    }
}

// ---------------- block reductions ----------------
__device__ __forceinline__ float blockSum128(float v, float* red) {
    int tid = threadIdx.x;
    red[tid] = v;
    __syncthreads();
    for (int s = 64; s; s >>= 1) {
        if (tid < s) red[tid] += red[tid + s];
        __syncthreads();
    }
    float r = red[0];
    __syncthreads();
    return r;
}
__device__ __forceinline__ float blockMax128(float v, float* red) {
    int tid = threadIdx.x;
    red[tid] = v;
    __syncthreads();
    for (int s = 64; s; s >>= 1) {
        if (tid < s) red[tid] = fmaxf(red[tid], red[tid + s]);
        __syncthreads();
    }
    float r = red[0];
    __syncthreads();
    return r;
}

// ---------------- phase B: softmax + weighted sum + residual + LN ----------
__global__ __launch_bounds__(128) void pair_reduce_ln(
    const float* __restrict__ lng, const float* __restrict__ lnb) {
    __shared__ float red[128];
    __shared__ float ws[NN];
    const int bi = blockIdx.x;
    const int i = bi % NN;
    const int tid = threadIdx.x;
    const int np = i + 1;
    const float* srow = g_s + (size_t)bi * NN;

    float lm = -1e30f;
    for (int j = tid; j < np; j += 128) lm = fmaxf(lm, srow[j]);
    float m = blockMax128(lm, red);

    float dsum = 0.f;
    for (int j = tid; j < np; j += 128) {
        float w = expf(srow[j] - m);
        ws[j] = w;
        dsum += w;
    }
    float den = blockSum128(dsum, red);

    const float* prow = g_p + (size_t)bi * NN * DD;
    float acc = 0.f;
#pragma unroll 4
    for (int j = 0; j < np; j++) acc += ws[j] * prow[(size_t)j * DD + tid];

    float v = g_x[bi * DD + tid] + acc / den;
    float mean = blockSum128(v, red) * (1.0f / DD);
    float dv = v - mean;
    float var = blockSum128(dv * dv, red) * (1.0f / DD);
    g_x[bi * DD + tid] = dv * rsqrtf(var + 1e-5f) * lng[tid] + lnb[tid];
}

// ---------------- FFN residual + LN ----------------
__global__ __launch_bounds__(128) void add_ln(
    const float* __restrict__ lng, const float* __restrict__ lnb) {
    __shared__ float red[128];
    const int bi = blockIdx.x;
    const int tid = threadIdx.x;
    float v = g_x[bi * DD + tid] + g_y[bi * DD + tid];
    float mean = blockSum128(v, red) * (1.0f / DD);
    float dv = v - mean;
    float var = blockSum128(dv * dv, red) * (1.0f / DD);
    g_x[bi * DD + tid] = dv * rsqrtf(var + 1e-5f) * lng[tid] + lnb[tid];
}

// ---------------- launcher ----------------
extern "C" void kernel_launch(void* const* d_in, const int* in_sizes, int n_in,
                              void* d_out, int out_size) {
    const int* ids = (const int*)d_in[0];
    const float* embw = (const float*)d_in[1];
    const float* pos = (const float*)d_in[2];
    const float* pW1 = (const float*)d_in[3];
    const float* pb1 = (const float*)d_in[4];
    const float* pW2 = (const float*)d_in[5];
    const float* pb2 = (const float*)d_in[6];
    const float* pW3 = (const float*)d_in[7];
    const float* pb3 = (const float*)d_in[8];
    const float* ln1g = (const float*)d_in[9];
    const float* ln1b = (const float*)d_in[10];
    const float* fW1 = (const float*)d_in[11];
    const float* fb1 = (const float*)d_in[12];
    const float* fW2 = (const float*)d_in[13];
    const float* fb2 = (const float*)d_in[14];
    const float* ln2g = (const float*)d_in[15];
    const float* ln2b = (const float*)d_in[16];
    const float* headW = (const float*)d_in[17];
    const float* headb = (const float*)d_in[18];
    float* out = (float*)d_out;

    cudaFuncSetAttribute(pair_mma, cudaFuncAttributeMaxDynamicSharedMemorySize,
                         PM_SMEM_BYTES);
    cudaFuncSetAttribute(head_mma, cudaFuncAttributeMaxDynamicSharedMemorySize,
                         HD_SMEM_BYTES);

    float *xp, *ap, *cp, *hp, *yp;
    cudaGetSymbolAddress((void**)&xp, g_x);
    cudaGetSymbolAddress((void**)&ap, g_a);
    cudaGetSymbolAddress((void**)&cp, g_c);
    cudaGetSymbolAddress((void**)&hp, g_h);
    cudaGetSymbolAddress((void**)&yp, g_y);

    embed_kernel<<<(BB * NN * DD + 255) / 256, 256>>>(ids, embw, pos);

    for (int l = 0; l < LL; l++) {
        gemm64<0><<<dim3(256 / 64, 768 / 64), 256>>>(
            xp, pW1 + (size_t)l * 256 * 256, pb1 + l * 256, ap, 128, 128, 256, 256);
        gemm64<0><<<dim3(256 / 64, 768 / 64), 256>>>(
            xp, pW1 + (size_t)l * 256 * 256 + 128 * 256, nullptr, cp, 128, 128, 256, 256);
        pair_mma<<<PGRID, 512, PM_SMEM_BYTES>>>(
            pW2 + (size_t)l * 256 * 128, pb2 + l * 128,
            pW3 + (size_t)l * 128 * 128, pb3 + l * 128);
        pair_reduce_ln<<<BB * NN, 128>>>(ln1g + l * 128, ln1b + l * 128);
        gemm64<1><<<dim3(512 / 64, 768 / 64), 256>>>(
            xp, fW1 + (size_t)l * 128 * 512, fb1 + l * 512, hp, 128, 128, 512, 512);
        gemm64<0><<<dim3(128 / 64, 768 / 64), 256>>>(
            hp, fW2 + (size_t)l * 512 * 128, fb2 + l * 128, yp, 512, 512, 128, 128);
        add_ln<<<BB * NN, 128>>>(ln2g + l * 128, ln2b + l * 128);
    }

    head_mma<<<dim3(VV / 128, 768 / 128), 256, HD_SMEM_BYTES>>>(headW, headb, out);
}

// round 5
// speedup vs baseline: 1.0776x; 1.0776x over previous
#include <cuda_runtime.h>
#include <cuda_fp16.h>
#include <math.h>
#include <stdint.h>

// Problem constants
#define BB 2
#define NN 384
#define DD 128
#define VV 8192
#define LL 2
#define NPAIR_B 73920
#define NPAIR_T 147840
#define PT 128
#define NTILES_MMA 1155      // 147840 / 128

// ---------------- scratch ----------------
__device__ float g_x[BB * NN * DD];
__device__ float g_a[BB * NN * 256];
__device__ float g_c[BB * NN * 256];
__device__ float g_h[BB * NN * 512];
__device__ float g_y[BB * NN * DD];
__device__ float g_p[(size_t)BB * NN * NN * DD];
__device__ float g_s[BB * NN * NN];
__device__ __half g_w2h[LL * 256 * 128];
__device__ __half g_w3h[LL * 128 * 128];

// exact gelu via A&S 7.1.26 erf (max abs err 1.5e-7)
__device__ __forceinline__ float gelu_fast(float x) {
    float y = fabsf(x) * 0.70710678118654752f;
    float q = fmaf(0.3275911f, y, 1.0f);
    float t;
    asm("rcp.approx.f32 %0, %1;" : "=f"(t) : "f"(q));
    float p = fmaf(fmaf(fmaf(fmaf(1.061405429f, t, -1.453152027f), t,
                             1.421413741f), t, -0.284496736f), t, 0.254829592f) * t;
    float e = __expf(-y * y);
    float erf_abs = fmaf(-p, e, 1.0f);
    float s = copysignf(erf_abs, x);
    return 0.5f * x * (1.0f + s);
}

__device__ __forceinline__ void ldsm4(uint32_t* r, uint32_t addr) {
    asm volatile("ldmatrix.sync.aligned.m8n8.x4.shared.b16 {%0,%1,%2,%3}, [%4];"
                 : "=r"(r[0]), "=r"(r[1]), "=r"(r[2]), "=r"(r[3]) : "r"(addr));
}
__device__ __forceinline__ void ldsm4t(uint32_t* r, uint32_t addr) {
    asm volatile("ldmatrix.sync.aligned.m8n8.x4.trans.shared.b16 {%0,%1,%2,%3}, [%4];"
                 : "=r"(r[0]), "=r"(r[1]), "=r"(r[2]), "=r"(r[3]) : "r"(addr));
}
__device__ __forceinline__ void mma_f16(float c[4], const uint32_t a[4],
                                        uint32_t b0, uint32_t b1) {
    asm volatile(
        "mma.sync.aligned.m16n8k16.row.col.f32.f16.f16.f32 "
        "{%0,%1,%2,%3}, {%4,%5,%6,%7}, {%8,%9}, {%0,%1,%2,%3};"
        : "+f"(c[0]), "+f"(c[1]), "+f"(c[2]), "+f"(c[3])
        : "r"(a[0]), "r"(a[1]), "r"(a[2]), "r"(a[3]), "r"(b0), "r"(b1));
}
__device__ __forceinline__ void cpa16(uint32_t daddr, const void* g) {
    asm volatile("cp.async.cg.shared.global [%0], [%1], 16;" :: "r"(daddr), "l"(g));
}
#define CP_COMMIT asm volatile("cp.async.commit_group;")
#define CP_WAIT0 asm volatile("cp.async.wait_group 0;")

// ---------------- weight pre-convert ----------------
__global__ void convert_w(const float* __restrict__ pW2, const float* __restrict__ pW3) {
    int t = blockIdx.x * 256 + threadIdx.x;
    const int n2 = LL * 256 * 128;
    const int n3 = LL * 128 * 128;
    if (t < n2) g_w2h[t] = __float2half(pW2[t]);
    int t3 = t - n2;
    if (t3 >= 0 && t3 < n3) g_w3h[t3] = __float2half(pW3[t3]);
}

// ---------------- embedding ----------------
__global__ void embed_kernel(const int* __restrict__ ids,
                             const float* __restrict__ emb,
                             const float* __restrict__ pos) {
    int t = blockIdx.x * blockDim.x + threadIdx.x;
    if (t >= BB * NN * DD) return;
    int d = t & (DD - 1);
    int bn = t >> 7;
    int n = bn % NN;
    g_x[t] = emb[ids[bn] * DD + d] + pos[n * DD + d];
}

// ---------------- generic 64x64x16 fp32 GEMM ----------------
template <int ACT>
__global__ __launch_bounds__(256) void gemm64(
    const float* __restrict__ A, const float* __restrict__ W,
    const float* __restrict__ bias, float* __restrict__ C,
    int K, int ldA, int ldW, int ldC) {
    __shared__ float As[16][64];
    __shared__ float Ws[16][64];
    const int bm = blockIdx.y * 64;
    const int bn = blockIdx.x * 64;
    const int tid = threadIdx.x;

    const int ar = tid >> 2;
    const int ak = (tid & 3) * 4;
    const int wk = tid >> 4;
    const int wn = (tid & 15) * 4;
    const int tm = (tid >> 4) * 4;
    const int tn = (tid & 15) * 4;

    float acc[4][4] = {};
    for (int k0 = 0; k0 < K; k0 += 16) {
        float4 av = *(const float4*)&A[(size_t)(bm + ar) * ldA + k0 + ak];
        As[ak + 0][ar] = av.x;
        As[ak + 1][ar] = av.y;
        As[ak + 2][ar] = av.z;
        As[ak + 3][ar] = av.w;
        *(float4*)&Ws[wk][wn] = *(const float4*)&W[(size_t)(k0 + wk) * ldW + bn + wn];
        __syncthreads();
#pragma unroll
        for (int k = 0; k < 16; k++) {
            float4 a = *(const float4*)&As[k][tm];
            float4 w = *(const float4*)&Ws[k][tn];
            acc[0][0] += a.x * w.x; acc[0][1] += a.x * w.y; acc[0][2] += a.x * w.z; acc[0][3] += a.x * w.w;
            acc[1][0] += a.y * w.x; acc[1][1] += a.y * w.y; acc[1][2] += a.y * w.z; acc[1][3] += a.y * w.w;
            acc[2][0] += a.z * w.x; acc[2][1] += a.z * w.y; acc[2][2] += a.z * w.z; acc[2][3] += a.z * w.w;
            acc[3][0] += a.w * w.x; acc[3][1] += a.w * w.y; acc[3][2] += a.w * w.z; acc[3][3] += a.w * w.w;
        }
        __syncthreads();
    }
    float4 bv = make_float4(0.f, 0.f, 0.f, 0.f);
    if (bias) bv = *(const float4*)&bias[bn + tn];
#pragma unroll
    for (int r = 0; r < 4; r++) {
        float4 o;
        o.x = acc[r][0] + bv.x;
        o.y = acc[r][1] + bv.y;
        o.z = acc[r][2] + bv.z;
        o.w = acc[r][3] + bv.w;
        if (ACT == 1) {
            o.x = gelu_fast(o.x); o.y = gelu_fast(o.y);
            o.z = gelu_fast(o.z); o.w = gelu_fast(o.w);
        }
        *(float4*)&C[(size_t)(bm + tm + r) * ldC + bn + tn] = o;
    }
}

// ---------------- pair kernel: chunked, cp.async dbl-buffered W, fp16 mma ---
// strides in halves: row-addr shifts 4 banks/row -> conflict-free ldmatrix
#define SA 72     // H1 [128][64]+pad
#define SBW 136   // W chunk [64][128]+pad
#define SH 136    // H2 [128][128]+pad
#define SPF 132   // Pf fp32 stride (floats)
// byte offsets
#define OWB0 0
#define OWB1 17408
#define OH1 34816
#define OH2 53248
#define OB2 88064
#define OB3 88576
#define ORA 89088
#define ORC 89600
#define OPO 90112
#define PM_SMEM_BYTES 90624
// Pf (fp32 [128][132] = 67584 B) overlays [0,67584): Wbuf+H1+part of H2 (all dead)

__global__ __launch_bounds__(256, 2) void pair_mma(
    const __half* __restrict__ W2h, const float* __restrict__ b2,
    const __half* __restrict__ W3h, const float* __restrict__ b3) {
    extern __shared__ char smc[];
    __half* H1s = (__half*)(smc + OH1);
    __half* H2s = (__half*)(smc + OH2);
    float* Pf = (float*)smc;
    float* b2s = (float*)(smc + OB2);
    float* b3s = (float*)(smc + OB3);
    int* rowA = (int*)(smc + ORA);
    int* rowC = (int*)(smc + ORC);
    int* poff = (int*)(smc + OPO);

    const int tid = threadIdx.x;
    const int lane = tid & 31;
    const int warp = tid >> 5;
    const int wm = warp >> 1;      // 0..3 -> M base 32*wm
    const int wn = warp & 1;       // 0..1 -> N base 64*wn
    const int lr = lane >> 2;
    const int lc = lane & 3;
    const int lrow = (lane & 7) + ((lane >> 3) & 1) * 8;
    const int lcol = (lane >> 4) * 8;

    const uint32_t sb = (uint32_t)__cvta_generic_to_shared(smc);
    const uint32_t h1_lane = sb + OH1 + (uint32_t)(lrow * SA + lcol) * 2;
    const uint32_t h2_lane = sb + OH2 + (uint32_t)(lrow * SH + lcol) * 2;
    const uint32_t w_lane0 = sb + OWB0 + (uint32_t)(lrow * SBW + lcol) * 2;
    const uint32_t w_lane1 = sb + OWB1 + (uint32_t)(lrow * SBW + lcol) * 2;

    // issue W2 chunk 0 -> buf0 (overlaps decode + H1 build)
    {
        const __half* src = W2h;
        uint32_t dbase = sb + OWB0;
#pragma unroll
        for (int e = tid; e < 1024; e += 256) {
            int row = e >> 4, seg = e & 15;
            cpa16(dbase + row * (SBW * 2) + seg * 16, src + row * 128 + seg * 8);
        }
        CP_COMMIT;
    }

    if (tid < 128) {
        b2s[tid] = b2[tid];
        b3s[tid] = b3[tid];
        int g = blockIdx.x * PT + tid;
        int b = (g >= NPAIR_B) ? 1 : 0;
        int idx = g - b * NPAIR_B;
        int i = (int)((sqrtf(8.0f * (float)idx + 1.0f) - 1.0f) * 0.5f);
        while ((i + 1) * (i + 2) / 2 <= idx) ++i;
        while (i * (i + 1) / 2 > idx) --i;
        int j = idx - i * (i + 1) / 2;
        rowA[tid] = b * NN + i;
        rowC[tid] = b * NN + j;
        poff[tid] = (b * NN + i) * NN + j;
    }
    __syncthreads();

    // build H1 chunk 0
#pragma unroll
    for (int e = tid; e < 128 * 16; e += 256) {
        int r = e >> 4, c4 = e & 15;
        const float4 av = *(const float4*)&g_a[rowA[r] * 256 + c4 * 4];
        const float4 cv = *(const float4*)&g_c[rowC[r] * 256 + c4 * 4];
        __half2* d = (__half2*)(H1s + r * SA + c4 * 4);
        d[0] = __floats2half2_rn(gelu_fast(av.x + cv.x), gelu_fast(av.y + cv.y));
        d[1] = __floats2half2_rn(gelu_fast(av.z + cv.z), gelu_fast(av.w + cv.w));
    }
    CP_WAIT0;
    __syncthreads();

    float acc[2][8][4] = {};
    uint32_t af[2][4];
    uint32_t bf[4];

    // ---------- GEMM1: K=256, 4 chunks of 64, W dbl-buffered ----------
    for (int kc = 0; kc < 4; kc++) {
        if (kc < 3) {   // prefetch next W2 chunk into other buffer
            const __half* src = W2h + (kc + 1) * 64 * 128;
            uint32_t dbase = sb + (((kc + 1) & 1) ? OWB1 : OWB0);
#pragma unroll
            for (int e = tid; e < 1024; e += 256) {
                int row = e >> 4, seg = e & 15;
                cpa16(dbase + row * (SBW * 2) + seg * 16, src + row * 128 + seg * 8);
            }
            CP_COMMIT;
        }
        const uint32_t wl = (kc & 1) ? w_lane1 : w_lane0;
#pragma unroll
        for (int ks = 0; ks < 4; ks++) {
            const int kb = ks * 16;
            ldsm4(af[0], h1_lane + (uint32_t)((wm * 32) * SA + kb) * 2);
            ldsm4(af[1], h1_lane + (uint32_t)((wm * 32 + 16) * SA + kb) * 2);
#pragma unroll
            for (int bt = 0; bt < 4; bt++) {
                ldsm4t(bf, wl + (uint32_t)(kb * SBW + wn * 64 + bt * 16) * 2);
                mma_f16(acc[0][2 * bt], af[0], bf[0], bf[1]);
                mma_f16(acc[1][2 * bt], af[1], bf[0], bf[1]);
                mma_f16(acc[0][2 * bt + 1], af[0], bf[2], bf[3]);
                mma_f16(acc[1][2 * bt + 1], af[1], bf[2], bf[3]);
            }
        }
        __syncthreads();   // all reads of H1s done
        if (kc < 3) {
            const int k0 = (kc + 1) * 64;
#pragma unroll
            for (int e = tid; e < 128 * 16; e += 256) {
                int r = e >> 4, c4 = e & 15;
                const float4 av = *(const float4*)&g_a[rowA[r] * 256 + k0 + c4 * 4];
                const float4 cv = *(const float4*)&g_c[rowC[r] * 256 + k0 + c4 * 4];
                __half2* d = (__half2*)(H1s + r * SA + c4 * 4);
                d[0] = __floats2half2_rn(gelu_fast(av.x + cv.x), gelu_fast(av.y + cv.y));
                d[1] = __floats2half2_rn(gelu_fast(av.z + cv.z), gelu_fast(av.w + cv.w));
            }
            CP_WAIT0;      // next W chunk landed
            __syncthreads();
        }
    }

    // prefetch BOTH W3 chunks (fills both buffers) — overlaps epilogue 1
#pragma unroll
    for (int ch = 0; ch < 2; ch++) {
        const __half* src = W3h + ch * 64 * 128;
        uint32_t dbase = sb + (ch ? OWB1 : OWB0);
#pragma unroll
        for (int e = tid; e < 1024; e += 256) {
            int row = e >> 4, seg = e & 15;
            cpa16(dbase + row * (SBW * 2) + seg * 16, src + row * 128 + seg * 8);
        }
        CP_COMMIT;
    }

    // epilogue 1: +b2, gelu, half -> H2s
#pragma unroll
    for (int mt = 0; mt < 2; mt++) {
        int r0 = wm * 32 + mt * 16 + lr;
#pragma unroll
        for (int nt = 0; nt < 8; nt++) {
            int cb = wn * 64 + nt * 8 + 2 * lc;
            float bx = b2s[cb], by = b2s[cb + 1];
            *(__half2*)(H2s + r0 * SH + cb) =
                __floats2half2_rn(gelu_fast(acc[mt][nt][0] + bx), gelu_fast(acc[mt][nt][1] + by));
            *(__half2*)(H2s + (r0 + 8) * SH + cb) =
                __floats2half2_rn(gelu_fast(acc[mt][nt][2] + bx), gelu_fast(acc[mt][nt][3] + by));
        }
    }
    CP_WAIT0;
    __syncthreads();

    // ---------- GEMM2: K=128, 8 uninterrupted k-steps ----------
    float acc2[2][8][4] = {};
#pragma unroll
    for (int ks = 0; ks < 8; ks++) {
        const int kbg = ks * 16;
        const uint32_t wl = (kbg & 64) ? w_lane1 : w_lane0;
        const int kb = kbg & 63;
        ldsm4(af[0], h2_lane + (uint32_t)((wm * 32) * SH + kbg) * 2);
        ldsm4(af[1], h2_lane + (uint32_t)((wm * 32 + 16) * SH + kbg) * 2);
#pragma unroll
        for (int bt = 0; bt < 4; bt++) {
            ldsm4t(bf, wl + (uint32_t)(kb * SBW + wn * 64 + bt * 16) * 2);
            mma_f16(acc2[0][2 * bt], af[0], bf[0], bf[1]);
            mma_f16(acc2[1][2 * bt], af[1], bf[0], bf[1]);
            mma_f16(acc2[0][2 * bt + 1], af[0], bf[2], bf[3]);
            mma_f16(acc2[1][2 * bt + 1], af[1], bf[2], bf[3]);
        }
    }
    __syncthreads();

    // epilogue 2: +b3 -> Pf (overlays dead Wbuf/H1/H2-prefix)
#pragma unroll
    for (int mt = 0; mt < 2; mt++) {
        int r0 = wm * 32 + mt * 16 + lr;
#pragma unroll
        for (int nt = 0; nt < 8; nt++) {
            int cb = wn * 64 + nt * 8 + 2 * lc;
            float bx = b3s[cb], by = b3s[cb + 1];
            *(float2*)(Pf + r0 * SPF + cb) =
                make_float2(acc2[mt][nt][0] + bx, acc2[mt][nt][1] + by);
            *(float2*)(Pf + (r0 + 8) * SPF + cb) =
                make_float2(acc2[mt][nt][2] + bx, acc2[mt][nt][3] + by);
        }
    }
    __syncthreads();

    // writeout: 2 threads per pair-row + norm
    {
        int r = tid >> 1, half = tid & 1;
        const float* src = Pf + r * SPF + half * 64;
        float* dst = g_p + (size_t)poff[r] * DD + half * 64;
        float ss = 0.f;
#pragma unroll
        for (int q = 0; q < 64; q += 4) {
            float4 v = *(const float4*)(src + q);
            *(float4*)(dst + q) = v;
            ss += v.x * v.x + v.y * v.y + v.z * v.z + v.w * v.w;
        }
        ss += __shfl_xor_sync(0xffffffffu, ss, 1);
        if (!half) g_s[poff[r]] = sqrtf(fmaxf(ss, 1e-30f));
    }
}

// ---------------- head: fp16 mma, 128x128 tiles ----------------
#define OHX 0
#define OHW 34816
#define OHB 69632
#define HD_SMEM_BYTES 70144

__global__ __launch_bounds__(256) void head_mma(
    const float* __restrict__ headW, const float* __restrict__ headb,
    float* __restrict__ out) {
    extern __shared__ char smc[];
    __half* Xh = (__half*)(smc + OHX);
    __half* Wh = (__half*)(smc + OHW);
    float* biass = (float*)(smc + OHB);
    float* Pf = (float*)smc;

    const int tid = threadIdx.x;
    const int lane = tid & 31;
    const int warp = tid >> 5;
    const int wm = warp >> 1;
    const int wn = warp & 1;
    const int lr = lane >> 2;
    const int lc = lane & 3;
    const int lrow = (lane & 7) + ((lane >> 3) & 1) * 8;
    const int lcol = (lane >> 4) * 8;

    const int n0 = blockIdx.x * 128;
    const int m0 = blockIdx.y * 128;

    const uint32_t sb = (uint32_t)__cvta_generic_to_shared(smc);
    const uint32_t x_lane = sb + OHX + (uint32_t)(lrow * SBW + lcol) * 2;
    const uint32_t w_lane = sb + OHW + (uint32_t)(lrow * SBW + lcol) * 2;

    for (int e = tid; e < 128 * 32; e += 256) {
        int r = e >> 5, c4 = e & 31;
        const float4 v = *(const float4*)&g_x[(m0 + r) * DD + c4 * 4];
        __half2* d = (__half2*)(Xh + r * SBW + c4 * 4);
        d[0] = __floats2half2_rn(v.x, v.y);
        d[1] = __floats2half2_rn(v.z, v.w);
    }
    for (int e = tid; e < 128 * 32; e += 256) {
        int k = e >> 5, n4 = e & 31;
        const float4 v = *(const float4*)&headW[(size_t)k * VV + n0 + n4 * 4];
        __half2* d = (__half2*)(Wh + k * SBW + n4 * 4);
        d[0] = __floats2half2_rn(v.x, v.y);
        d[1] = __floats2half2_rn(v.z, v.w);
    }
    if (tid < 128) biass[tid] = headb[n0 + tid];
    __syncthreads();

    float acc[2][8][4] = {};
    uint32_t af[2][4];
    uint32_t bf[4];
#pragma unroll
    for (int ks = 0; ks < 8; ks++) {
        const int kb = ks * 16;
        ldsm4(af[0], x_lane + (uint32_t)((wm * 32) * SBW + kb) * 2);
        ldsm4(af[1], x_lane + (uint32_t)((wm * 32 + 16) * SBW + kb) * 2);
#pragma unroll
        for (int bt = 0; bt < 4; bt++) {
            ldsm4t(bf, w_lane + (uint32_t)(kb * SBW + wn * 64 + bt * 16) * 2);
            mma_f16(acc[0][2 * bt], af[0], bf[0], bf[1]);
            mma_f16(acc[1][2 * bt], af[1], bf[0], bf[1]);
            mma_f16(acc[0][2 * bt + 1], af[0], bf[2], bf[3]);
            mma_f16(acc[1][2 * bt + 1], af[1], bf[2], bf[3]);
        }
    }
    __syncthreads();

#pragma unroll
    for (int mt = 0; mt < 2; mt++) {
        int r0 = wm * 32 + mt * 16 + lr;
#pragma unroll
        for (int nt = 0; nt < 8; nt++) {
            int cb = wn * 64 + nt * 8 + 2 * lc;
            float bx = biass[cb], by = biass[cb + 1];
            *(float2*)(Pf + r0 * SPF + cb) =
                make_float2(acc[mt][nt][0] + bx, acc[mt][nt][1] + by);
            *(float2*)(Pf + (r0 + 8) * SPF + cb) =
                make_float2(acc[mt][nt][2] + bx, acc[mt][nt][3] + by);
        }
    }
    __syncthreads();

    {
        int r = tid >> 1, hf = tid & 1;
        const float* src = Pf + r * SPF + hf * 64;
        float* dst = out + (size_t)(m0 + r) * VV + n0 + hf * 64;
#pragma unroll
        for (int u = 0; u < 64; u += 4)
            *(float4*)(dst + u) = *(const float4*)(src + u);
    }
}

// ---------------- block reductions ----------------
__device__ __forceinline__ float blockSum128(float v, float* red) {
    int tid = threadIdx.x;
    red[tid] = v;
    __syncthreads();
    for (int s = 64; s; s >>= 1) {
        if (tid < s) red[tid] += red[tid + s];
        __syncthreads();
    }
    float r = red[0];
    __syncthreads();
    return r;
}
__device__ __forceinline__ float blockMax128(float v, float* red) {
    int tid = threadIdx.x;
    red[tid] = v;
    __syncthreads();
    for (int s = 64; s; s >>= 1) {
        if (tid < s) red[tid] = fmaxf(red[tid], red[tid + s]);
        __syncthreads();
    }
    float r = red[0];
    __syncthreads();
    return r;
}

// ---------------- phase B: softmax + weighted sum + residual + LN ----------
__global__ __launch_bounds__(128) void pair_reduce_ln(
    const float* __restrict__ lng, const float* __restrict__ lnb) {
    __shared__ float red[128];
    __shared__ float ws[NN];
    const int bi = blockIdx.x;
    const int i = bi % NN;
    const int tid = threadIdx.x;
    const int np = i + 1;
    const float* srow = g_s + (size_t)bi * NN;

    float lm = -1e30f;
    for (int j = tid; j < np; j += 128) lm = fmaxf(lm, srow[j]);
    float m = blockMax128(lm, red);

    float dsum = 0.f;
    for (int j = tid; j < np; j += 128) {
        float w = expf(srow[j] - m);
        ws[j] = w;
        dsum += w;
    }
    float den = blockSum128(dsum, red);

    const float* prow = g_p + (size_t)bi * NN * DD;
    float acc = 0.f;
#pragma unroll 4
    for (int j = 0; j < np; j++) acc += ws[j] * prow[(size_t)j * DD + tid];

    float v = g_x[bi * DD + tid] + acc / den;
    float mean = blockSum128(v, red) * (1.0f / DD);
    float dv = v - mean;
    float var = blockSum128(dv * dv, red) * (1.0f / DD);
    g_x[bi * DD + tid] = dv * rsqrtf(var + 1e-5f) * lng[tid] + lnb[tid];
}

// ---------------- FFN residual + LN ----------------
__global__ __launch_bounds__(128) void add_ln(
    const float* __restrict__ lng, const float* __restrict__ lnb) {
    __shared__ float red[128];
    const int bi = blockIdx.x;
    const int tid = threadIdx.x;
    float v = g_x[bi * DD + tid] + g_y[bi * DD + tid];
    float mean = blockSum128(v, red) * (1.0f / DD);
    float dv = v - mean;
    float var = blockSum128(dv * dv, red) * (1.0f / DD);
    g_x[bi * DD + tid] = dv * rsqrtf(var + 1e-5f) * lng[tid] + lnb[tid];
}

// ---------------- launcher ----------------
extern "C" void kernel_launch(void* const* d_in, const int* in_sizes, int n_in,
                              void* d_out, int out_size) {
    const int* ids = (const int*)d_in[0];
    const float* embw = (const float*)d_in[1];
    const float* pos = (const float*)d_in[2];
    const float* pW1 = (const float*)d_in[3];
    const float* pb1 = (const float*)d_in[4];
    const float* pW2 = (const float*)d_in[5];
    const float* pb2 = (const float*)d_in[6];
    const float* pW3 = (const float*)d_in[7];
    const float* pb3 = (const float*)d_in[8];
    const float* ln1g = (const float*)d_in[9];
    const float* ln1b = (const float*)d_in[10];
    const float* fW1 = (const float*)d_in[11];
    const float* fb1 = (const float*)d_in[12];
    const float* fW2 = (const float*)d_in[13];
    const float* fb2 = (const float*)d_in[14];
    const float* ln2g = (const float*)d_in[15];
    const float* ln2b = (const float*)d_in[16];
    const float* headW = (const float*)d_in[17];
    const float* headb = (const float*)d_in[18];
    float* out = (float*)d_out;

    cudaFuncSetAttribute(pair_mma, cudaFuncAttributeMaxDynamicSharedMemorySize,
                         PM_SMEM_BYTES);
    cudaFuncSetAttribute(head_mma, cudaFuncAttributeMaxDynamicSharedMemorySize,
                         HD_SMEM_BYTES);

    float *xp, *ap, *cp, *hp, *yp;
    cudaGetSymbolAddress((void**)&xp, g_x);
    cudaGetSymbolAddress((void**)&ap, g_a);
    cudaGetSymbolAddress((void**)&cp, g_c);
    cudaGetSymbolAddress((void**)&hp, g_h);
    cudaGetSymbolAddress((void**)&yp, g_y);
    __half *w2hp, *w3hp;
    cudaGetSymbolAddress((void**)&w2hp, g_w2h);
    cudaGetSymbolAddress((void**)&w3hp, g_w3h);

    embed_kernel<<<(BB * NN * DD + 255) / 256, 256>>>(ids, embw, pos);
    convert_w<<<(LL * 256 * 128 + LL * 128 * 128 + 255) / 256, 256>>>(pW2, pW3);

    for (int l = 0; l < LL; l++) {
        gemm64<0><<<dim3(256 / 64, 768 / 64), 256>>>(
            xp, pW1 + (size_t)l * 256 * 256, pb1 + l * 256, ap, 128, 128, 256, 256);
        gemm64<0><<<dim3(256 / 64, 768 / 64), 256>>>(
            xp, pW1 + (size_t)l * 256 * 256 + 128 * 256, nullptr, cp, 128, 128, 256, 256);
        pair_mma<<<NTILES_MMA, 256, PM_SMEM_BYTES>>>(
            w2hp + (size_t)l * 256 * 128, pb2 + l * 128,
            w3hp + (size_t)l * 128 * 128, pb3 + l * 128);
        pair_reduce_ln<<<BB * NN, 128>>>(ln1g + l * 128, ln1b + l * 128);
        gemm64<1><<<dim3(512 / 64, 768 / 64), 256>>>(
            xp, fW1 + (size_t)l * 128 * 512, fb1 + l * 512, hp, 128, 128, 512, 512);
        gemm64<0><<<dim3(128 / 64, 768 / 64), 256>>>(
            hp, fW2 + (size_t)l * 512 * 128, fb2 + l * 128, yp, 512, 512, 128, 128);
        add_ln<<<BB * NN, 128>>>(ln2g + l * 128, ln2b + l * 128);
    }

    head_mma<<<dim3(VV / 128, 768 / 128), 256, HD_SMEM_BYTES>>>(headW, headb, out);
}

// round 6
// speedup vs baseline: 1.2411x; 1.1517x over previous
#include <cuda_runtime.h>
#include <cuda_fp16.h>
#include <math.h>
#include <stdint.h>

// Problem constants
#define BB 2
#define NN 384
#define DD 128
#define VV 8192
#define LL 2
#define NPAIR_B 73920
#define NPAIR_T 147840
#define PT 128
#define NTILES_MMA 1155      // 147840 / 128

// ---------------- scratch ----------------
__device__ float g_x[BB * NN * DD];
__device__ float g_a[BB * NN * 256];
__device__ float g_c[BB * NN * 256];
__device__ float g_h[BB * NN * 512];
__device__ float g_y[BB * NN * DD];
__device__ float g_p[(size_t)BB * NN * NN * DD];
__device__ float g_s[BB * NN * NN];
__device__ __half g_w2h[LL * 256 * 128];
__device__ __half g_w3h[LL * 128 * 128];

// exact gelu via A&S 7.1.26 erf (max abs err 1.5e-7)
__device__ __forceinline__ float gelu_fast(float x) {
    float y = fabsf(x) * 0.70710678118654752f;
    float q = fmaf(0.3275911f, y, 1.0f);
    float t;
    asm("rcp.approx.f32 %0, %1;" : "=f"(t) : "f"(q));
    float p = fmaf(fmaf(fmaf(fmaf(1.061405429f, t, -1.453152027f), t,
                             1.421413741f), t, -0.284496736f), t, 0.254829592f) * t;
    float e = __expf(-y * y);
    float erf_abs = fmaf(-p, e, 1.0f);
    float s = copysignf(erf_abs, x);
    return 0.5f * x * (1.0f + s);
}

__device__ __forceinline__ void ldsm4(uint32_t* r, uint32_t addr) {
    asm volatile("ldmatrix.sync.aligned.m8n8.x4.shared.b16 {%0,%1,%2,%3}, [%4];"
                 : "=r"(r[0]), "=r"(r[1]), "=r"(r[2]), "=r"(r[3]) : "r"(addr));
}
__device__ __forceinline__ void ldsm4t(uint32_t* r, uint32_t addr) {
    asm volatile("ldmatrix.sync.aligned.m8n8.x4.trans.shared.b16 {%0,%1,%2,%3}, [%4];"
                 : "=r"(r[0]), "=r"(r[1]), "=r"(r[2]), "=r"(r[3]) : "r"(addr));
}
__device__ __forceinline__ void mma_f16(float c[4], const uint32_t a[4],
                                        uint32_t b0, uint32_t b1) {
    asm volatile(
        "mma.sync.aligned.m16n8k16.row.col.f32.f16.f16.f32 "
        "{%0,%1,%2,%3}, {%4,%5,%6,%7}, {%8,%9}, {%0,%1,%2,%3};"
        : "+f"(c[0]), "+f"(c[1]), "+f"(c[2]), "+f"(c[3])
        : "r"(a[0]), "r"(a[1]), "r"(a[2]), "r"(a[3]), "r"(b0), "r"(b1));
}
__device__ __forceinline__ void cpa16(uint32_t daddr, const void* g) {
    asm volatile("cp.async.cg.shared.global [%0], [%1], 16;" :: "r"(daddr), "l"(g));
}
#define CP_COMMIT asm volatile("cp.async.commit_group;")
#define CP_WAIT0 asm volatile("cp.async.wait_group 0;")

// ---------------- weight pre-convert ----------------
__global__ void convert_w(const float* __restrict__ pW2, const float* __restrict__ pW3) {
    int t = blockIdx.x * 256 + threadIdx.x;
    const int n2 = LL * 256 * 128;
    const int n3 = LL * 128 * 128;
    if (t < n2) g_w2h[t] = __float2half(pW2[t]);
    int t3 = t - n2;
    if (t3 >= 0 && t3 < n3) g_w3h[t3] = __float2half(pW3[t3]);
}

// ---------------- embedding ----------------
__global__ void embed_kernel(const int* __restrict__ ids,
                             const float* __restrict__ emb,
                             const float* __restrict__ pos) {
    int t = blockIdx.x * blockDim.x + threadIdx.x;
    if (t >= BB * NN * DD) return;
    int d = t & (DD - 1);
    int bn = t >> 7;
    int n = bn % NN;
    g_x[t] = emb[ids[bn] * DD + d] + pos[n * DD + d];
}

// ================= generic fp16-mma GEMM, 64(M)x128(N) tiles ================
// C = act(A @ W + bias); supports split-N with two weight/bias/output sets
// (for the fused a/c computation). K must be a multiple of 128.
#define SBW 136   // smem stride in halves for [k][n] / [m][k] panels
#define SPF 132   // fp32 staging stride (floats)
#define GM_OX 0                    // Xh: 64*136*2   = 17408
#define GM_OW 17408                // Wh: 128*136*2  = 34816
#define GM_OB 52224                // bias: 512
#define GM_SMEM_BYTES 52736
// Pf overlay (64*132*4 = 33792 B) sits at offset 0 (dead Xh + part of Wh)

template <int ACT>
__global__ __launch_bounds__(256, 2) void gemm_mma64(
    const float* __restrict__ A, int ldA,
    const float* __restrict__ Wa, const float* __restrict__ Wb, int nsplit, int ldW,
    const float* __restrict__ ba, const float* __restrict__ bb,
    float* __restrict__ Ca, float* __restrict__ Cb, int ldC, int K) {
    extern __shared__ char smc[];
    __half* Xh = (__half*)(smc + GM_OX);
    __half* Wh = (__half*)(smc + GM_OW);
    float* biass = (float*)(smc + GM_OB);
    float* Pf = (float*)smc;

    const int tid = threadIdx.x;
    const int lane = tid & 31;
    const int warp = tid >> 5;
    const int wm = warp >> 2;      // 0..1 -> M base 32*wm
    const int wn = warp & 3;       // 0..3 -> N base 32*wn
    const int lr = lane >> 2;
    const int lc = lane & 3;
    const int lrow = (lane & 7) + ((lane >> 3) & 1) * 8;
    const int lcol = (lane >> 4) * 8;

    const int n0 = blockIdx.x * 128;
    const int m0 = blockIdx.y * 64;

    const float* Wsrc;
    const float* bsrc;
    float* Cdst;
    if (n0 < nsplit) {
        Wsrc = Wa + n0;
        bsrc = ba ? ba + n0 : nullptr;
        Cdst = Ca + n0;
    } else {
        int nn = n0 - nsplit;
        Wsrc = Wb + nn;
        bsrc = bb ? bb + nn : nullptr;
        Cdst = Cb + nn;
    }

    const uint32_t sb = (uint32_t)__cvta_generic_to_shared(smc);
    const uint32_t x_lane = sb + GM_OX + (uint32_t)(lrow * SBW + lcol) * 2;
    const uint32_t w_lane = sb + GM_OW + (uint32_t)(lrow * SBW + lcol) * 2;

    if (tid < 128) biass[tid] = bsrc ? bsrc[tid] : 0.f;

    float acc[2][4][4] = {};
    uint32_t af[2][4];
    uint32_t bf[4];

    const int nkc = K >> 7;
    for (int kc = 0; kc < nkc; kc++) {
        const int k0 = kc << 7;
        for (int e = tid; e < 64 * 32; e += 256) {
            int r = e >> 5, c4 = e & 31;
            const float4 v = *(const float4*)&A[(size_t)(m0 + r) * ldA + k0 + c4 * 4];
            __half2* d = (__half2*)(Xh + r * SBW + c4 * 4);
            d[0] = __floats2half2_rn(v.x, v.y);
            d[1] = __floats2half2_rn(v.z, v.w);
        }
        for (int e = tid; e < 128 * 32; e += 256) {
            int k = e >> 5, n4 = e & 31;
            const float4 v = *(const float4*)&Wsrc[(size_t)(k0 + k) * ldW + n4 * 4];
            __half2* d = (__half2*)(Wh + k * SBW + n4 * 4);
            d[0] = __floats2half2_rn(v.x, v.y);
            d[1] = __floats2half2_rn(v.z, v.w);
        }
        __syncthreads();
#pragma unroll
        for (int ks = 0; ks < 8; ks++) {
            const int kb = ks * 16;
            ldsm4(af[0], x_lane + (uint32_t)((wm * 32) * SBW + kb) * 2);
            ldsm4(af[1], x_lane + (uint32_t)((wm * 32 + 16) * SBW + kb) * 2);
#pragma unroll
            for (int bt = 0; bt < 2; bt++) {
                ldsm4t(bf, w_lane + (uint32_t)(kb * SBW + wn * 32 + bt * 16) * 2);
                mma_f16(acc[0][2 * bt], af[0], bf[0], bf[1]);
                mma_f16(acc[1][2 * bt], af[1], bf[0], bf[1]);
                mma_f16(acc[0][2 * bt + 1], af[0], bf[2], bf[3]);
                mma_f16(acc[1][2 * bt + 1], af[1], bf[2], bf[3]);
            }
        }
        __syncthreads();
    }

    // epilogue: +bias, act, stage to Pf
#pragma unroll
    for (int mt = 0; mt < 2; mt++) {
        int r0 = wm * 32 + mt * 16 + lr;
#pragma unroll
        for (int nt = 0; nt < 4; nt++) {
            int cb = wn * 32 + nt * 8 + 2 * lc;
            float o0 = acc[mt][nt][0] + biass[cb];
            float o1 = acc[mt][nt][1] + biass[cb + 1];
            float o2 = acc[mt][nt][2] + biass[cb];
            float o3 = acc[mt][nt][3] + biass[cb + 1];
            if (ACT == 1) {
                o0 = gelu_fast(o0); o1 = gelu_fast(o1);
                o2 = gelu_fast(o2); o3 = gelu_fast(o3);
            }
            *(float2*)(Pf + r0 * SPF + cb) = make_float2(o0, o1);
            *(float2*)(Pf + (r0 + 8) * SPF + cb) = make_float2(o2, o3);
        }
    }
    __syncthreads();

    // coalesced writeout: 4 threads per row (32 cols each)
    {
        int r = tid >> 2, q = tid & 3;
        const float* src = Pf + r * SPF + q * 32;
        float* dst = Cdst + (size_t)(m0 + r) * ldC + q * 32;
#pragma unroll
        for (int u = 0; u < 32; u += 4)
            *(float4*)(dst + u) = *(const float4*)(src + u);
    }
}

// ---------------- pair kernel: chunked, cp.async dbl-buffered W, fp16 mma ---
#define SA 72     // H1 [128][64]+pad
#define SH 136    // H2 [128][128]+pad
#define OWB0 0
#define OWB1 17408
#define OH1 34816
#define OH2 53248
#define OB2 88064
#define OB3 88576
#define ORA 89088
#define ORC 89600
#define OPO 90112
#define PM_SMEM_BYTES 90624

__global__ __launch_bounds__(256, 2) void pair_mma(
    const __half* __restrict__ W2h, const float* __restrict__ b2,
    const __half* __restrict__ W3h, const float* __restrict__ b3) {
    extern __shared__ char smc[];
    __half* H1s = (__half*)(smc + OH1);
    __half* H2s = (__half*)(smc + OH2);
    float* Pf = (float*)smc;
    float* b2s = (float*)(smc + OB2);
    float* b3s = (float*)(smc + OB3);
    int* rowA = (int*)(smc + ORA);
    int* rowC = (int*)(smc + ORC);
    int* poff = (int*)(smc + OPO);

    const int tid = threadIdx.x;
    const int lane = tid & 31;
    const int warp = tid >> 5;
    const int wm = warp >> 1;
    const int wn = warp & 1;
    const int lr = lane >> 2;
    const int lc = lane & 3;
    const int lrow = (lane & 7) + ((lane >> 3) & 1) * 8;
    const int lcol = (lane >> 4) * 8;

    const uint32_t sb = (uint32_t)__cvta_generic_to_shared(smc);
    const uint32_t h1_lane = sb + OH1 + (uint32_t)(lrow * SA + lcol) * 2;
    const uint32_t h2_lane = sb + OH2 + (uint32_t)(lrow * SH + lcol) * 2;
    const uint32_t w_lane0 = sb + OWB0 + (uint32_t)(lrow * SBW + lcol) * 2;
    const uint32_t w_lane1 = sb + OWB1 + (uint32_t)(lrow * SBW + lcol) * 2;

    {
        const __half* src = W2h;
        uint32_t dbase = sb + OWB0;
#pragma unroll
        for (int e = tid; e < 1024; e += 256) {
            int row = e >> 4, seg = e & 15;
            cpa16(dbase + row * (SBW * 2) + seg * 16, src + row * 128 + seg * 8);
        }
        CP_COMMIT;
    }

    if (tid < 128) {
        b2s[tid] = b2[tid];
        b3s[tid] = b3[tid];
        int g = blockIdx.x * PT + tid;
        int b = (g >= NPAIR_B) ? 1 : 0;
        int idx = g - b * NPAIR_B;
        int i = (int)((sqrtf(8.0f * (float)idx + 1.0f) - 1.0f) * 0.5f);
        while ((i + 1) * (i + 2) / 2 <= idx) ++i;
        while (i * (i + 1) / 2 > idx) --i;
        int j = idx - i * (i + 1) / 2;
        rowA[tid] = b * NN + i;
        rowC[tid] = b * NN + j;
        poff[tid] = (b * NN + i) * NN + j;
    }
    __syncthreads();

#pragma unroll
    for (int e = tid; e < 128 * 16; e += 256) {
        int r = e >> 4, c4 = e & 15;
        const float4 av = *(const float4*)&g_a[rowA[r] * 256 + c4 * 4];
        const float4 cv = *(const float4*)&g_c[rowC[r] * 256 + c4 * 4];
        __half2* d = (__half2*)(H1s + r * SA + c4 * 4);
        d[0] = __floats2half2_rn(gelu_fast(av.x + cv.x), gelu_fast(av.y + cv.y));
        d[1] = __floats2half2_rn(gelu_fast(av.z + cv.z), gelu_fast(av.w + cv.w));
    }
    CP_WAIT0;
    __syncthreads();

    float acc[2][8][4] = {};
    uint32_t af[2][4];
    uint32_t bf[4];

    for (int kc = 0; kc < 4; kc++) {
        if (kc < 3) {
            const __half* src = W2h + (kc + 1) * 64 * 128;
            uint32_t dbase = sb + (((kc + 1) & 1) ? OWB1 : OWB0);
#pragma unroll
            for (int e = tid; e < 1024; e += 256) {
                int row = e >> 4, seg = e & 15;
                cpa16(dbase + row * (SBW * 2) + seg * 16, src + row * 128 + seg * 8);
            }
            CP_COMMIT;
        }
        const uint32_t wl = (kc & 1) ? w_lane1 : w_lane0;
#pragma unroll
        for (int ks = 0; ks < 4; ks++) {
            const int kb = ks * 16;
            ldsm4(af[0], h1_lane + (uint32_t)((wm * 32) * SA + kb) * 2);
            ldsm4(af[1], h1_lane + (uint32_t)((wm * 32 + 16) * SA + kb) * 2);
#pragma unroll
            for (int bt = 0; bt < 4; bt++) {
                ldsm4t(bf, wl + (uint32_t)(kb * SBW + wn * 64 + bt * 16) * 2);
                mma_f16(acc[0][2 * bt], af[0], bf[0], bf[1]);
                mma_f16(acc[1][2 * bt], af[1], bf[0], bf[1]);
                mma_f16(acc[0][2 * bt + 1], af[0], bf[2], bf[3]);
                mma_f16(acc[1][2 * bt + 1], af[1], bf[2], bf[3]);
            }
        }
        __syncthreads();
        if (kc < 3) {
            const int k0 = (kc + 1) * 64;
#pragma unroll
            for (int e = tid; e < 128 * 16; e += 256) {
                int r = e >> 4, c4 = e & 15;
                const float4 av = *(const float4*)&g_a[rowA[r] * 256 + k0 + c4 * 4];
                const float4 cv = *(const float4*)&g_c[rowC[r] * 256 + k0 + c4 * 4];
                __half2* d = (__half2*)(H1s + r * SA + c4 * 4);
                d[0] = __floats2half2_rn(gelu_fast(av.x + cv.x), gelu_fast(av.y + cv.y));
                d[1] = __floats2half2_rn(gelu_fast(av.z + cv.z), gelu_fast(av.w + cv.w));
            }
            CP_WAIT0;
            __syncthreads();
        }
    }

#pragma unroll
    for (int ch = 0; ch < 2; ch++) {
        const __half* src = W3h + ch * 64 * 128;
        uint32_t dbase = sb + (ch ? OWB1 : OWB0);
#pragma unroll
        for (int e = tid; e < 1024; e += 256) {
            int row = e >> 4, seg = e & 15;
            cpa16(dbase + row * (SBW * 2) + seg * 16, src + row * 128 + seg * 8);
        }
        CP_COMMIT;
    }

#pragma unroll
    for (int mt = 0; mt < 2; mt++) {
        int r0 = wm * 32 + mt * 16 + lr;
#pragma unroll
        for (int nt = 0; nt < 8; nt++) {
            int cb = wn * 64 + nt * 8 + 2 * lc;
            float bx = b2s[cb], by = b2s[cb + 1];
            *(__half2*)(H2s + r0 * SH + cb) =
                __floats2half2_rn(gelu_fast(acc[mt][nt][0] + bx), gelu_fast(acc[mt][nt][1] + by));
            *(__half2*)(H2s + (r0 + 8) * SH + cb) =
                __floats2half2_rn(gelu_fast(acc[mt][nt][2] + bx), gelu_fast(acc[mt][nt][3] + by));
        }
    }
    CP_WAIT0;
    __syncthreads();

    float acc2[2][8][4] = {};
#pragma unroll
    for (int ks = 0; ks < 8; ks++) {
        const int kbg = ks * 16;
        const uint32_t wl = (kbg & 64) ? w_lane1 : w_lane0;
        const int kb = kbg & 63;
        ldsm4(af[0], h2_lane + (uint32_t)((wm * 32) * SH + kbg) * 2);
        ldsm4(af[1], h2_lane + (uint32_t)((wm * 32 + 16) * SH + kbg) * 2);
#pragma unroll
        for (int bt = 0; bt < 4; bt++) {
            ldsm4t(bf, wl + (uint32_t)(kb * SBW + wn * 64 + bt * 16) * 2);
            mma_f16(acc2[0][2 * bt], af[0], bf[0], bf[1]);
            mma_f16(acc2[1][2 * bt], af[1], bf[0], bf[1]);
            mma_f16(acc2[0][2 * bt + 1], af[0], bf[2], bf[3]);
            mma_f16(acc2[1][2 * bt + 1], af[1], bf[2], bf[3]);
        }
    }
    __syncthreads();

#pragma unroll
    for (int mt = 0; mt < 2; mt++) {
        int r0 = wm * 32 + mt * 16 + lr;
#pragma unroll
        for (int nt = 0; nt < 8; nt++) {
            int cb = wn * 64 + nt * 8 + 2 * lc;
            float bx = b3s[cb], by = b3s[cb + 1];
            *(float2*)(Pf + r0 * SPF + cb) =
                make_float2(acc2[mt][nt][0] + bx, acc2[mt][nt][1] + by);
            *(float2*)(Pf + (r0 + 8) * SPF + cb) =
                make_float2(acc2[mt][nt][2] + bx, acc2[mt][nt][3] + by);
        }
    }
    __syncthreads();

    {
        int r = tid >> 1, half = tid & 1;
        const float* src = Pf + r * SPF + half * 64;
        float* dst = g_p + (size_t)poff[r] * DD + half * 64;
        float ss = 0.f;
#pragma unroll
        for (int q = 0; q < 64; q += 4) {
            float4 v = *(const float4*)(src + q);
            *(float4*)(dst + q) = v;
            ss += v.x * v.x + v.y * v.y + v.z * v.z + v.w * v.w;
        }
        ss += __shfl_xor_sync(0xffffffffu, ss, 1);
        if (!half) g_s[poff[r]] = sqrtf(fmaxf(ss, 1e-30f));
    }
}

// ---------------- head: fp16 mma, 128x128 tiles ----------------
#define OHX 0
#define OHW 34816
#define OHB 69632
#define HD_SMEM_BYTES 70144

__global__ __launch_bounds__(256) void head_mma(
    const float* __restrict__ headW, const float* __restrict__ headb,
    float* __restrict__ out) {
    extern __shared__ char smc[];
    __half* Xh = (__half*)(smc + OHX);
    __half* Wh = (__half*)(smc + OHW);
    float* biass = (float*)(smc + OHB);
    float* Pf = (float*)smc;

    const int tid = threadIdx.x;
    const int lane = tid & 31;
    const int warp = tid >> 5;
    const int wm = warp >> 1;
    const int wn = warp & 1;
    const int lr = lane >> 2;
    const int lc = lane & 3;
    const int lrow = (lane & 7) + ((lane >> 3) & 1) * 8;
    const int lcol = (lane >> 4) * 8;

    const int n0 = blockIdx.x * 128;
    const int m0 = blockIdx.y * 128;

    const uint32_t sb = (uint32_t)__cvta_generic_to_shared(smc);
    const uint32_t x_lane = sb + OHX + (uint32_t)(lrow * SBW + lcol) * 2;
    const uint32_t w_lane = sb + OHW + (uint32_t)(lrow * SBW + lcol) * 2;

    for (int e = tid; e < 128 * 32; e += 256) {
        int r = e >> 5, c4 = e & 31;
        const float4 v = *(const float4*)&g_x[(m0 + r) * DD + c4 * 4];
        __half2* d = (__half2*)(Xh + r * SBW + c4 * 4);
        d[0] = __floats2half2_rn(v.x, v.y);
        d[1] = __floats2half2_rn(v.z, v.w);
    }
    for (int e = tid; e < 128 * 32; e += 256) {
        int k = e >> 5, n4 = e & 31;
        const float4 v = *(const float4*)&headW[(size_t)k * VV + n0 + n4 * 4];
        __half2* d = (__half2*)(Wh + k * SBW + n4 * 4);
        d[0] = __floats2half2_rn(v.x, v.y);
        d[1] = __floats2half2_rn(v.z, v.w);
    }
    if (tid < 128) biass[tid] = headb[n0 + tid];
    __syncthreads();

    float acc[2][8][4] = {};
    uint32_t af[2][4];
    uint32_t bf[4];
#pragma unroll
    for (int ks = 0; ks < 8; ks++) {
        const int kb = ks * 16;
        ldsm4(af[0], x_lane + (uint32_t)((wm * 32) * SBW + kb) * 2);
        ldsm4(af[1], x_lane + (uint32_t)((wm * 32 + 16) * SBW + kb) * 2);
#pragma unroll
        for (int bt = 0; bt < 4; bt++) {
            ldsm4t(bf, w_lane + (uint32_t)(kb * SBW + wn * 64 + bt * 16) * 2);
            mma_f16(acc[0][2 * bt], af[0], bf[0], bf[1]);
            mma_f16(acc[1][2 * bt], af[1], bf[0], bf[1]);
            mma_f16(acc[0][2 * bt + 1], af[0], bf[2], bf[3]);
            mma_f16(acc[1][2 * bt + 1], af[1], bf[2], bf[3]);
        }
    }
    __syncthreads();

#pragma unroll
    for (int mt = 0; mt < 2; mt++) {
        int r0 = wm * 32 + mt * 16 + lr;
#pragma unroll
        for (int nt = 0; nt < 8; nt++) {
            int cb = wn * 64 + nt * 8 + 2 * lc;
            float bx = biass[cb], by = biass[cb + 1];
            *(float2*)(Pf + r0 * SPF + cb) =
                make_float2(acc[mt][nt][0] + bx, acc[mt][nt][1] + by);
            *(float2*)(Pf + (r0 + 8) * SPF + cb) =
                make_float2(acc[mt][nt][2] + bx, acc[mt][nt][3] + by);
        }
    }
    __syncthreads();

    {
        int r = tid >> 1, hf = tid & 1;
        const float* src = Pf + r * SPF + hf * 64;
        float* dst = out + (size_t)(m0 + r) * VV + n0 + hf * 64;
#pragma unroll
        for (int u = 0; u < 64; u += 4)
            *(float4*)(dst + u) = *(const float4*)(src + u);
    }
}

// ---------------- 512-wide block reductions ----------------
__device__ __forceinline__ float blockSum512(float v, float* red) {
    int tid = threadIdx.x;
    red[tid] = v;
    __syncthreads();
    for (int s = 256; s; s >>= 1) {
        if (tid < s) red[tid] += red[tid + s];
        __syncthreads();
    }
    float r = red[0];
    __syncthreads();
    return r;
}
__device__ __forceinline__ float blockMax512(float v, float* red) {
    int tid = threadIdx.x;
    red[tid] = v;
    __syncthreads();
    for (int s = 256; s; s >>= 1) {
        if (tid < s) red[tid] = fmaxf(red[tid], red[tid + s]);
        __syncthreads();
    }
    float r = red[0];
    __syncthreads();
    return r;
}
__device__ __forceinline__ float blockSum128(float v, float* red) {
    int tid = threadIdx.x;
    red[tid] = v;
    __syncthreads();
    for (int s = 64; s; s >>= 1) {
        if (tid < s) red[tid] += red[tid + s];
        __syncthreads();
    }
    float r = red[0];
    __syncthreads();
    return r;
}

// ---------------- phase B: softmax + weighted sum + residual + LN ----------
// 512 threads: 4 j-groups x 128 d-lanes (4x parallelism on the serial j loop)
__global__ __launch_bounds__(512) void pair_reduce_ln(
    const float* __restrict__ lng, const float* __restrict__ lnb) {
    __shared__ float red[512];
    __shared__ float ws[NN];
    __shared__ float accbuf[4][128];
    const int bi = blockIdx.x;
    const int i = bi % NN;
    const int tid = threadIdx.x;
    const int gid = tid >> 7;
    const int d = tid & 127;
    const int np = i + 1;
    const float* srow = g_s + (size_t)bi * NN;

    float lm = -1e30f;
    for (int j = tid; j < np; j += 512) lm = fmaxf(lm, srow[j]);
    float m = blockMax512(lm, red);

    float dsum = 0.f;
    for (int j = tid; j < np; j += 512) {
        float w = expf(srow[j] - m);
        ws[j] = w;
        dsum += w;
    }
    float den = blockSum512(dsum, red);   // barrier -> ws visible

    const float* prow = g_p + (size_t)bi * NN * DD;
    float acc = 0.f;
#pragma unroll 2
    for (int j = gid; j < np; j += 4) acc += ws[j] * prow[(size_t)j * DD + d];
    accbuf[gid][d] = acc;
    __syncthreads();

    float v = 0.f;
    if (gid == 0)
        v = g_x[bi * DD + d] +
            (accbuf[0][d] + accbuf[1][d] + accbuf[2][d] + accbuf[3][d]) / den;

    float mean = blockSum512(gid == 0 ? v : 0.f, red) * (1.0f / DD);
    float dv = v - mean;
    float var = blockSum512(gid == 0 ? dv * dv : 0.f, red) * (1.0f / DD);
    if (gid == 0)
        g_x[bi * DD + d] = dv * rsqrtf(var + 1e-5f) * lng[d] + lnb[d];
}

// ---------------- FFN residual + LN ----------------
__global__ __launch_bounds__(128) void add_ln(
    const float* __restrict__ lng, const float* __restrict__ lnb) {
    __shared__ float red[128];
    const int bi = blockIdx.x;
    const int tid = threadIdx.x;
    float v = g_x[bi * DD + tid] + g_y[bi * DD + tid];
    float mean = blockSum128(v, red) * (1.0f / DD);
    float dv = v - mean;
    float var = blockSum128(dv * dv, red) * (1.0f / DD);
    g_x[bi * DD + tid] = dv * rsqrtf(var + 1e-5f) * lng[tid] + lnb[tid];
}

// ---------------- launcher ----------------
extern "C" void kernel_launch(void* const* d_in, const int* in_sizes, int n_in,
                              void* d_out, int out_size) {
    const int* ids = (const int*)d_in[0];
    const float* embw = (const float*)d_in[1];
    const float* pos = (const float*)d_in[2];
    const float* pW1 = (const float*)d_in[3];
    const float* pb1 = (const float*)d_in[4];
    const float* pW2 = (const float*)d_in[5];
    const float* pb2 = (const float*)d_in[6];
    const float* pW3 = (const float*)d_in[7];
    const float* pb3 = (const float*)d_in[8];
    const float* ln1g = (const float*)d_in[9];
    const float* ln1b = (const float*)d_in[10];
    const float* fW1 = (const float*)d_in[11];
    const float* fb1 = (const float*)d_in[12];
    const float* fW2 = (const float*)d_in[13];
    const float* fb2 = (const float*)d_in[14];
    const float* ln2g = (const float*)d_in[15];
    const float* ln2b = (const float*)d_in[16];
    const float* headW = (const float*)d_in[17];
    const float* headb = (const float*)d_in[18];
    float* out = (float*)d_out;

    cudaFuncSetAttribute(pair_mma, cudaFuncAttributeMaxDynamicSharedMemorySize,
                         PM_SMEM_BYTES);
    cudaFuncSetAttribute(head_mma, cudaFuncAttributeMaxDynamicSharedMemorySize,
                         HD_SMEM_BYTES);
    cudaFuncSetAttribute(gemm_mma64<0>, cudaFuncAttributeMaxDynamicSharedMemorySize,
                         GM_SMEM_BYTES);
    cudaFuncSetAttribute(gemm_mma64<1>, cudaFuncAttributeMaxDynamicSharedMemorySize,
                         GM_SMEM_BYTES);

    float *xp, *ap, *cp, *hp, *yp;
    cudaGetSymbolAddress((void**)&xp, g_x);
    cudaGetSymbolAddress((void**)&ap, g_a);
    cudaGetSymbolAddress((void**)&cp, g_c);
    cudaGetSymbolAddress((void**)&hp, g_h);
    cudaGetSymbolAddress((void**)&yp, g_y);
    __half *w2hp, *w3hp;
    cudaGetSymbolAddress((void**)&w2hp, g_w2h);
    cudaGetSymbolAddress((void**)&w3hp, g_w3h);

    embed_kernel<<<(BB * NN * DD + 255) / 256, 256>>>(ids, embw, pos);
    convert_w<<<(LL * 256 * 128 + LL * 128 * 128 + 255) / 256, 256>>>(pW2, pW3);

    for (int l = 0; l < LL; l++) {
        const float* W1l = pW1 + (size_t)l * 256 * 256;
        // fused a/c: [768,512] output split across g_a / g_c at n=256
        gemm_mma64<0><<<dim3(4, 12), 256, GM_SMEM_BYTES>>>(
            xp, 128, W1l, W1l + 128 * 256, 256, 256,
            pb1 + l * 256, nullptr, ap, cp, 256, 128);
        pair_mma<<<NTILES_MMA, 256, PM_SMEM_BYTES>>>(
            w2hp + (size_t)l * 256 * 128, pb2 + l * 128,
            w3hp + (size_t)l * 128 * 128, pb3 + l * 128);
        pair_reduce_ln<<<BB * NN, 512>>>(ln1g + l * 128, ln1b + l * 128);
        // FFN1: gelu(x @ fW1 + fb1) -> g_h [768,512]
        gemm_mma64<1><<<dim3(4, 12), 256, GM_SMEM_BYTES>>>(
            xp, 128, fW1 + (size_t)l * 128 * 512, nullptr, 1 << 30, 512,
            fb1 + l * 512, nullptr, hp, nullptr, 512, 128);
        // FFN2: g_h @ fW2 + fb2 -> g_y [768,128]
        gemm_mma64<0><<<dim3(1, 12), 256, GM_SMEM_BYTES>>>(
            hp, 512, fW2 + (size_t)l * 512 * 128, nullptr, 1 << 30, 128,
            fb2 + l * 128, nullptr, yp, nullptr, 128, 512);
        add_ln<<<BB * NN, 128>>>(ln2g + l * 128, ln2b + l * 128);
    }

    head_mma<<<dim3(VV / 128, 768 / 128), 256, HD_SMEM_BYTES>>>(headW, headb, out);
}

// round 7
// speedup vs baseline: 1.4510x; 1.1691x over previous
#include <cuda_runtime.h>
#include <cuda_fp16.h>
#include <math.h>
#include <stdint.h>

// Problem constants
#define BB 2
#define NN 384
#define DD 128
#define VV 8192
#define LL 2
#define NPAIR_B 73920
#define NPAIR_T 147840
#define PT 128
#define NTILES_MMA 1155      // 147840 / 128

// ---------------- scratch ----------------
__device__ float g_x[BB * NN * DD];
__device__ float g_a[BB * NN * 256];
__device__ float g_c[BB * NN * 256];
__device__ float g_h[BB * NN * 512];
__device__ float g_y[BB * NN * DD];
__device__ float g_p[(size_t)BB * NN * NN * DD];
__device__ float g_s[BB * NN * NN];
__device__ __half g_w2h[LL * 256 * 128];
__device__ __half g_w3h[LL * 128 * 128];

// tanh-form gelu using HW MUFU.TANH: 4 fma/mul + 1 MUFU
__device__ __forceinline__ float gelu_fast(float x) {
    float x2 = x * x;
    float inner = fmaf(0.0356774081f, x2, 0.7978845608f);
    float u = x * inner;
    float t;
    asm("tanh.approx.f32 %0, %1;" : "=f"(t) : "f"(u));
    float hx = 0.5f * x;
    return fmaf(hx, t, hx);
}

__device__ __forceinline__ void ldsm4(uint32_t* r, uint32_t addr) {
    asm volatile("ldmatrix.sync.aligned.m8n8.x4.shared.b16 {%0,%1,%2,%3}, [%4];"
                 : "=r"(r[0]), "=r"(r[1]), "=r"(r[2]), "=r"(r[3]) : "r"(addr));
}
__device__ __forceinline__ void ldsm4t(uint32_t* r, uint32_t addr) {
    asm volatile("ldmatrix.sync.aligned.m8n8.x4.trans.shared.b16 {%0,%1,%2,%3}, [%4];"
                 : "=r"(r[0]), "=r"(r[1]), "=r"(r[2]), "=r"(r[3]) : "r"(addr));
}
__device__ __forceinline__ void mma_f16(float c[4], const uint32_t a[4],
                                        uint32_t b0, uint32_t b1) {
    asm volatile(
        "mma.sync.aligned.m16n8k16.row.col.f32.f16.f16.f32 "
        "{%0,%1,%2,%3}, {%4,%5,%6,%7}, {%8,%9}, {%0,%1,%2,%3};"
        : "+f"(c[0]), "+f"(c[1]), "+f"(c[2]), "+f"(c[3])
        : "r"(a[0]), "r"(a[1]), "r"(a[2]), "r"(a[3]), "r"(b0), "r"(b1));
}
__device__ __forceinline__ void cpa16(uint32_t daddr, const void* g) {
    asm volatile("cp.async.cg.shared.global [%0], [%1], 16;" :: "r"(daddr), "l"(g));
}
#define CP_COMMIT asm volatile("cp.async.commit_group;")
#define CP_WAIT0 asm volatile("cp.async.wait_group 0;")

// ---------------- weight pre-convert ----------------
__global__ void convert_w(const float* __restrict__ pW2, const float* __restrict__ pW3) {
    int t = blockIdx.x * 256 + threadIdx.x;
    const int n2 = LL * 256 * 128;
    const int n3 = LL * 128 * 128;
    if (t < n2) g_w2h[t] = __float2half(pW2[t]);
    int t3 = t - n2;
    if (t3 >= 0 && t3 < n3) g_w3h[t3] = __float2half(pW3[t3]);
}

// ---------------- embedding ----------------
__global__ void embed_kernel(const int* __restrict__ ids,
                             const float* __restrict__ emb,
                             const float* __restrict__ pos) {
    int t = blockIdx.x * blockDim.x + threadIdx.x;
    if (t >= BB * NN * DD) return;
    int d = t & (DD - 1);
    int bn = t >> 7;
    int n = bn % NN;
    g_x[t] = emb[ids[bn] * DD + d] + pos[n * DD + d];
}

// ================= generic fp16-mma GEMM, 64(M)x128(N) tiles ================
#define SBW 136
#define SPF 132
#define GM_OX 0
#define GM_OW 17408
#define GM_OB 52224
#define GM_SMEM_BYTES 52736

template <int ACT>
__global__ __launch_bounds__(256, 2) void gemm_mma64(
    const float* __restrict__ A, int ldA,
    const float* __restrict__ Wa, const float* __restrict__ Wb, int nsplit, int ldW,
    const float* __restrict__ ba, const float* __restrict__ bb,
    float* __restrict__ Ca, float* __restrict__ Cb, int ldC, int K) {
    extern __shared__ char smc[];
    __half* Xh = (__half*)(smc + GM_OX);
    __half* Wh = (__half*)(smc + GM_OW);
    float* biass = (float*)(smc + GM_OB);
    float* Pf = (float*)smc;

    const int tid = threadIdx.x;
    const int lane = tid & 31;
    const int warp = tid >> 5;
    const int wm = warp >> 2;
    const int wn = warp & 3;
    const int lr = lane >> 2;
    const int lc = lane & 3;
    const int lrow = (lane & 7) + ((lane >> 3) & 1) * 8;
    const int lcol = (lane >> 4) * 8;

    const int n0 = blockIdx.x * 128;
    const int m0 = blockIdx.y * 64;

    const float* Wsrc;
    const float* bsrc;
    float* Cdst;
    if (n0 < nsplit) {
        Wsrc = Wa + n0;
        bsrc = ba ? ba + n0 : nullptr;
        Cdst = Ca + n0;
    } else {
        int nn = n0 - nsplit;
        Wsrc = Wb + nn;
        bsrc = bb ? bb + nn : nullptr;
        Cdst = Cb + nn;
    }

    const uint32_t sb = (uint32_t)__cvta_generic_to_shared(smc);
    const uint32_t x_lane = sb + GM_OX + (uint32_t)(lrow * SBW + lcol) * 2;
    const uint32_t w_lane = sb + GM_OW + (uint32_t)(lrow * SBW + lcol) * 2;

    if (tid < 128) biass[tid] = bsrc ? bsrc[tid] : 0.f;

    float acc[2][4][4] = {};
    uint32_t af[2][4];
    uint32_t bf[4];

    const int nkc = K >> 7;
    for (int kc = 0; kc < nkc; kc++) {
        const int k0 = kc << 7;
        for (int e = tid; e < 64 * 32; e += 256) {
            int r = e >> 5, c4 = e & 31;
            const float4 v = *(const float4*)&A[(size_t)(m0 + r) * ldA + k0 + c4 * 4];
            __half2* d = (__half2*)(Xh + r * SBW + c4 * 4);
            d[0] = __floats2half2_rn(v.x, v.y);
            d[1] = __floats2half2_rn(v.z, v.w);
        }
        for (int e = tid; e < 128 * 32; e += 256) {
            int k = e >> 5, n4 = e & 31;
            const float4 v = *(const float4*)&Wsrc[(size_t)(k0 + k) * ldW + n4 * 4];
            __half2* d = (__half2*)(Wh + k * SBW + n4 * 4);
            d[0] = __floats2half2_rn(v.x, v.y);
            d[1] = __floats2half2_rn(v.z, v.w);
        }
        __syncthreads();
#pragma unroll
        for (int ks = 0; ks < 8; ks++) {
            const int kb = ks * 16;
            ldsm4(af[0], x_lane + (uint32_t)((wm * 32) * SBW + kb) * 2);
            ldsm4(af[1], x_lane + (uint32_t)((wm * 32 + 16) * SBW + kb) * 2);
#pragma unroll
            for (int bt = 0; bt < 2; bt++) {
                ldsm4t(bf, w_lane + (uint32_t)(kb * SBW + wn * 32 + bt * 16) * 2);
                mma_f16(acc[0][2 * bt], af[0], bf[0], bf[1]);
                mma_f16(acc[1][2 * bt], af[1], bf[0], bf[1]);
                mma_f16(acc[0][2 * bt + 1], af[0], bf[2], bf[3]);
                mma_f16(acc[1][2 * bt + 1], af[1], bf[2], bf[3]);
            }
        }
        __syncthreads();
    }

#pragma unroll
    for (int mt = 0; mt < 2; mt++) {
        int r0 = wm * 32 + mt * 16 + lr;
#pragma unroll
        for (int nt = 0; nt < 4; nt++) {
            int cb = wn * 32 + nt * 8 + 2 * lc;
            float o0 = acc[mt][nt][0] + biass[cb];
            float o1 = acc[mt][nt][1] + biass[cb + 1];
            float o2 = acc[mt][nt][2] + biass[cb];
            float o3 = acc[mt][nt][3] + biass[cb + 1];
            if (ACT == 1) {
                o0 = gelu_fast(o0); o1 = gelu_fast(o1);
                o2 = gelu_fast(o2); o3 = gelu_fast(o3);
            }
            *(float2*)(Pf + r0 * SPF + cb) = make_float2(o0, o1);
            *(float2*)(Pf + (r0 + 8) * SPF + cb) = make_float2(o2, o3);
        }
    }
    __syncthreads();

    {
        int r = tid >> 2, q = tid & 3;
        const float* src = Pf + r * SPF + q * 32;
        float* dst = Cdst + (size_t)(m0 + r) * ldC + q * 32;
#pragma unroll
        for (int u = 0; u < 32; u += 4)
            *(float4*)(dst + u) = *(const float4*)(src + u);
    }
}

// ---------------- pair kernel: chunked, cp.async dbl-buffered W, fp16 mma ---
#define SA 72
#define SH 136
#define OWB0 0
#define OWB1 17408
#define OH1 34816
#define OH2 53248
#define OB2 88064
#define OB3 88576
#define ORA 89088
#define ORC 89600
#define OPO 90112
#define PM_SMEM_BYTES 90624

__global__ __launch_bounds__(256, 2) void pair_mma(
    const __half* __restrict__ W2h, const float* __restrict__ b2,
    const __half* __restrict__ W3h, const float* __restrict__ b3) {
    extern __shared__ char smc[];
    __half* H1s = (__half*)(smc + OH1);
    __half* H2s = (__half*)(smc + OH2);
    float* Pf = (float*)smc;
    float* b2s = (float*)(smc + OB2);
    float* b3s = (float*)(smc + OB3);
    int* rowA = (int*)(smc + ORA);
    int* rowC = (int*)(smc + ORC);
    int* poff = (int*)(smc + OPO);

    const int tid = threadIdx.x;
    const int lane = tid & 31;
    const int warp = tid >> 5;
    const int wm = warp >> 1;
    const int wn = warp & 1;
    const int lr = lane >> 2;
    const int lc = lane & 3;
    const int lrow = (lane & 7) + ((lane >> 3) & 1) * 8;
    const int lcol = (lane >> 4) * 8;

    const uint32_t sb = (uint32_t)__cvta_generic_to_shared(smc);
    const uint32_t h1_lane = sb + OH1 + (uint32_t)(lrow * SA + lcol) * 2;
    const uint32_t h2_lane = sb + OH2 + (uint32_t)(lrow * SH + lcol) * 2;
    const uint32_t w_lane0 = sb + OWB0 + (uint32_t)(lrow * SBW + lcol) * 2;
    const uint32_t w_lane1 = sb + OWB1 + (uint32_t)(lrow * SBW + lcol) * 2;

    {
        const __half* src = W2h;
        uint32_t dbase = sb + OWB0;
#pragma unroll
        for (int e = tid; e < 1024; e += 256) {
            int row = e >> 4, seg = e & 15;
            cpa16(dbase + row * (SBW * 2) + seg * 16, src + row * 128 + seg * 8);
        }
        CP_COMMIT;
    }

    if (tid < 128) {
        b2s[tid] = b2[tid];
        b3s[tid] = b3[tid];
        int g = blockIdx.x * PT + tid;
        int b = (g >= NPAIR_B) ? 1 : 0;
        int idx = g - b * NPAIR_B;
        int i = (int)((sqrtf(8.0f * (float)idx + 1.0f) - 1.0f) * 0.5f);
        while ((i + 1) * (i + 2) / 2 <= idx) ++i;
        while (i * (i + 1) / 2 > idx) --i;
        int j = idx - i * (i + 1) / 2;
        rowA[tid] = b * NN + i;
        rowC[tid] = b * NN + j;
        poff[tid] = (b * NN + i) * NN + j;
    }
    __syncthreads();

#pragma unroll
    for (int e = tid; e < 128 * 16; e += 256) {
        int r = e >> 4, c4 = e & 15;
        const float4 av = *(const float4*)&g_a[rowA[r] * 256 + c4 * 4];
        const float4 cv = *(const float4*)&g_c[rowC[r] * 256 + c4 * 4];
        __half2* d = (__half2*)(H1s + r * SA + c4 * 4);
        d[0] = __floats2half2_rn(gelu_fast(av.x + cv.x), gelu_fast(av.y + cv.y));
        d[1] = __floats2half2_rn(gelu_fast(av.z + cv.z), gelu_fast(av.w + cv.w));
    }
    CP_WAIT0;
    __syncthreads();

    float acc[2][8][4] = {};
    uint32_t af[2][4];
    uint32_t bf[4];

    for (int kc = 0; kc < 4; kc++) {
        if (kc < 3) {
            const __half* src = W2h + (kc + 1) * 64 * 128;
            uint32_t dbase = sb + (((kc + 1) & 1) ? OWB1 : OWB0);
#pragma unroll
            for (int e = tid; e < 1024; e += 256) {
                int row = e >> 4, seg = e & 15;
                cpa16(dbase + row * (SBW * 2) + seg * 16, src + row * 128 + seg * 8);
            }
            CP_COMMIT;
        }
        const uint32_t wl = (kc & 1) ? w_lane1 : w_lane0;
#pragma unroll
        for (int ks = 0; ks < 4; ks++) {
            const int kb = ks * 16;
            ldsm4(af[0], h1_lane + (uint32_t)((wm * 32) * SA + kb) * 2);
            ldsm4(af[1], h1_lane + (uint32_t)((wm * 32 + 16) * SA + kb) * 2);
#pragma unroll
            for (int bt = 0; bt < 4; bt++) {
                ldsm4t(bf, wl + (uint32_t)(kb * SBW + wn * 64 + bt * 16) * 2);
                mma_f16(acc[0][2 * bt], af[0], bf[0], bf[1]);
                mma_f16(acc[1][2 * bt], af[1], bf[0], bf[1]);
                mma_f16(acc[0][2 * bt + 1], af[0], bf[2], bf[3]);
                mma_f16(acc[1][2 * bt + 1], af[1], bf[2], bf[3]);
            }
        }
        __syncthreads();
        if (kc < 3) {
            const int k0 = (kc + 1) * 64;
#pragma unroll
            for (int e = tid; e < 128 * 16; e += 256) {
                int r = e >> 4, c4 = e & 15;
                const float4 av = *(const float4*)&g_a[rowA[r] * 256 + k0 + c4 * 4];
                const float4 cv = *(const float4*)&g_c[rowC[r] * 256 + k0 + c4 * 4];
                __half2* d = (__half2*)(H1s + r * SA + c4 * 4);
                d[0] = __floats2half2_rn(gelu_fast(av.x + cv.x), gelu_fast(av.y + cv.y));
                d[1] = __floats2half2_rn(gelu_fast(av.z + cv.z), gelu_fast(av.w + cv.w));
            }
            CP_WAIT0;
            __syncthreads();
        }
    }

#pragma unroll
    for (int ch = 0; ch < 2; ch++) {
        const __half* src = W3h + ch * 64 * 128;
        uint32_t dbase = sb + (ch ? OWB1 : OWB0);
#pragma unroll
        for (int e = tid; e < 1024; e += 256) {
            int row = e >> 4, seg = e & 15;
            cpa16(dbase + row * (SBW * 2) + seg * 16, src + row * 128 + seg * 8);
        }
        CP_COMMIT;
    }

#pragma unroll
    for (int mt = 0; mt < 2; mt++) {
        int r0 = wm * 32 + mt * 16 + lr;
#pragma unroll
        for (int nt = 0; nt < 8; nt++) {
            int cb = wn * 64 + nt * 8 + 2 * lc;
            float bx = b2s[cb], by = b2s[cb + 1];
            *(__half2*)(H2s + r0 * SH + cb) =
                __floats2half2_rn(gelu_fast(acc[mt][nt][0] + bx), gelu_fast(acc[mt][nt][1] + by));
            *(__half2*)(H2s + (r0 + 8) * SH + cb) =
                __floats2half2_rn(gelu_fast(acc[mt][nt][2] + bx), gelu_fast(acc[mt][nt][3] + by));
        }
    }
    CP_WAIT0;
    __syncthreads();

    float acc2[2][8][4] = {};
#pragma unroll
    for (int ks = 0; ks < 8; ks++) {
        const int kbg = ks * 16;
        const uint32_t wl = (kbg & 64) ? w_lane1 : w_lane0;
        const int kb = kbg & 63;
        ldsm4(af[0], h2_lane + (uint32_t)((wm * 32) * SH + kbg) * 2);
        ldsm4(af[1], h2_lane + (uint32_t)((wm * 32 + 16) * SH + kbg) * 2);
#pragma unroll
        for (int bt = 0; bt < 4; bt++) {
            ldsm4t(bf, wl + (uint32_t)(kb * SBW + wn * 64 + bt * 16) * 2);
            mma_f16(acc2[0][2 * bt], af[0], bf[0], bf[1]);
            mma_f16(acc2[1][2 * bt], af[1], bf[0], bf[1]);
            mma_f16(acc2[0][2 * bt + 1], af[0], bf[2], bf[3]);
            mma_f16(acc2[1][2 * bt + 1], af[1], bf[2], bf[3]);
        }
    }
    __syncthreads();

#pragma unroll
    for (int mt = 0; mt < 2; mt++) {
        int r0 = wm * 32 + mt * 16 + lr;
#pragma unroll
        for (int nt = 0; nt < 8; nt++) {
            int cb = wn * 64 + nt * 8 + 2 * lc;
            float bx = b3s[cb], by = b3s[cb + 1];
            *(float2*)(Pf + r0 * SPF + cb) =
                make_float2(acc2[mt][nt][0] + bx, acc2[mt][nt][1] + by);
            *(float2*)(Pf + (r0 + 8) * SPF + cb) =
                make_float2(acc2[mt][nt][2] + bx, acc2[mt][nt][3] + by);
        }
    }
    __syncthreads();

    {
        int r = tid >> 1, half = tid & 1;
        const float* src = Pf + r * SPF + half * 64;
        float* dst = g_p + (size_t)poff[r] * DD + half * 64;
        float ss = 0.f;
#pragma unroll
        for (int q = 0; q < 64; q += 4) {
            float4 v = *(const float4*)(src + q);
            *(float4*)(dst + q) = v;
            ss += v.x * v.x + v.y * v.y + v.z * v.z + v.w * v.w;
        }
        ss += __shfl_xor_sync(0xffffffffu, ss, 1);
        if (!half) g_s[poff[r]] = sqrtf(fmaxf(ss, 1e-30f));
    }
}

// ---------------- head: fp16 mma, 128x128 tiles ----------------
#define OHX 0
#define OHW 34816
#define OHB 69632
#define HD_SMEM_BYTES 70144

__global__ __launch_bounds__(256) void head_mma(
    const float* __restrict__ headW, const float* __restrict__ headb,
    float* __restrict__ out) {
    extern __shared__ char smc[];
    __half* Xh = (__half*)(smc + OHX);
    __half* Wh = (__half*)(smc + OHW);
    float* biass = (float*)(smc + OHB);
    float* Pf = (float*)smc;

    const int tid = threadIdx.x;
    const int lane = tid & 31;
    const int warp = tid >> 5;
    const int wm = warp >> 1;
    const int wn = warp & 1;
    const int lr = lane >> 2;
    const int lc = lane & 3;
    const int lrow = (lane & 7) + ((lane >> 3) & 1) * 8;
    const int lcol = (lane >> 4) * 8;

    const int n0 = blockIdx.x * 128;
    const int m0 = blockIdx.y * 128;

    const uint32_t sb = (uint32_t)__cvta_generic_to_shared(smc);
    const uint32_t x_lane = sb + OHX + (uint32_t)(lrow * SBW + lcol) * 2;
    const uint32_t w_lane = sb + OHW + (uint32_t)(lrow * SBW + lcol) * 2;

    for (int e = tid; e < 128 * 32; e += 256) {
        int r = e >> 5, c4 = e & 31;
        const float4 v = *(const float4*)&g_x[(m0 + r) * DD + c4 * 4];
        __half2* d = (__half2*)(Xh + r * SBW + c4 * 4);
        d[0] = __floats2half2_rn(v.x, v.y);
        d[1] = __floats2half2_rn(v.z, v.w);
    }
    for (int e = tid; e < 128 * 32; e += 256) {
        int k = e >> 5, n4 = e & 31;
        const float4 v = *(const float4*)&headW[(size_t)k * VV + n0 + n4 * 4];
        __half2* d = (__half2*)(Wh + k * SBW + n4 * 4);
        d[0] = __floats2half2_rn(v.x, v.y);
        d[1] = __floats2half2_rn(v.z, v.w);
    }
    if (tid < 128) biass[tid] = headb[n0 + tid];
    __syncthreads();

    float acc[2][8][4] = {};
    uint32_t af[2][4];
    uint32_t bf[4];
#pragma unroll
    for (int ks = 0; ks < 8; ks++) {
        const int kb = ks * 16;
        ldsm4(af[0], x_lane + (uint32_t)((wm * 32) * SBW + kb) * 2);
        ldsm4(af[1], x_lane + (uint32_t)((wm * 32 + 16) * SBW + kb) * 2);
#pragma unroll
        for (int bt = 0; bt < 4; bt++) {
            ldsm4t(bf, w_lane + (uint32_t)(kb * SBW + wn * 64 + bt * 16) * 2);
            mma_f16(acc[0][2 * bt], af[0], bf[0], bf[1]);
            mma_f16(acc[1][2 * bt], af[1], bf[0], bf[1]);
            mma_f16(acc[0][2 * bt + 1], af[0], bf[2], bf[3]);
            mma_f16(acc[1][2 * bt + 1], af[1], bf[2], bf[3]);
        }
    }
    __syncthreads();

#pragma unroll
    for (int mt = 0; mt < 2; mt++) {
        int r0 = wm * 32 + mt * 16 + lr;
#pragma unroll
        for (int nt = 0; nt < 8; nt++) {
            int cb = wn * 64 + nt * 8 + 2 * lc;
            float bx = biass[cb], by = biass[cb + 1];
            *(float2*)(Pf + r0 * SPF + cb) =
                make_float2(acc[mt][nt][0] + bx, acc[mt][nt][1] + by);
            *(float2*)(Pf + (r0 + 8) * SPF + cb) =
                make_float2(acc[mt][nt][2] + bx, acc[mt][nt][3] + by);
        }
    }
    __syncthreads();

    {
        int r = tid >> 1, hf = tid & 1;
        const float* src = Pf + r * SPF + hf * 64;
        float* dst = out + (size_t)(m0 + r) * VV + n0 + hf * 64;
#pragma unroll
        for (int u = 0; u < 64; u += 4)
            *(float4*)(dst + u) = *(const float4*)(src + u);
    }
}

// ---------------- 512-wide block reductions ----------------
__device__ __forceinline__ float blockSum512(float v, float* red) {
    int tid = threadIdx.x;
    red[tid] = v;
    __syncthreads();
    for (int s = 256; s; s >>= 1) {
        if (tid < s) red[tid] += red[tid + s];
        __syncthreads();
    }
    float r = red[0];
    __syncthreads();
    return r;
}
__device__ __forceinline__ float blockMax512(float v, float* red) {
    int tid = threadIdx.x;
    red[tid] = v;
    __syncthreads();
    for (int s = 256; s; s >>= 1) {
        if (tid < s) red[tid] = fmaxf(red[tid], red[tid + s]);
        __syncthreads();
    }
    float r = red[0];
    __syncthreads();
    return r;
}
__device__ __forceinline__ float blockSum128(float v, float* red) {
    int tid = threadIdx.x;
    red[tid] = v;
    __syncthreads();
    for (int s = 64; s; s >>= 1) {
        if (tid < s) red[tid] += red[tid + s];
        __syncthreads();
    }
    float r = red[0];
    __syncthreads();
    return r;
}

// ---------------- phase B: softmax + weighted sum + residual + LN ----------
__global__ __launch_bounds__(512) void pair_reduce_ln(
    const float* __restrict__ lng, const float* __restrict__ lnb) {
    __shared__ float red[512];
    __shared__ float ws[NN];
    __shared__ float accbuf[4][128];
    const int bi = blockIdx.x;
    const int i = bi % NN;
    const int tid = threadIdx.x;
    const int gid = tid >> 7;
    const int d = tid & 127;
    const int np = i + 1;
    const float* srow = g_s + (size_t)bi * NN;

    float lm = -1e30f;
    for (int j = tid; j < np; j += 512) lm = fmaxf(lm, srow[j]);
    float m = blockMax512(lm, red);

    float dsum = 0.f;
    for (int j = tid; j < np; j += 512) {
        float w = expf(srow[j] - m);
        ws[j] = w;
        dsum += w;
    }
    float den = blockSum512(dsum, red);

    const float* prow = g_p + (size_t)bi * NN * DD;
    float acc = 0.f;
#pragma unroll 2
    for (int j = gid; j < np; j += 4) acc += ws[j] * prow[(size_t)j * DD + d];
    accbuf[gid][d] = acc;
    __syncthreads();

    float v = 0.f;
    if (gid == 0)
        v = g_x[bi * DD + d] +
            (accbuf[0][d] + accbuf[1][d] + accbuf[2][d] + accbuf[3][d]) / den;

    float mean = blockSum512(gid == 0 ? v : 0.f, red) * (1.0f / DD);
    float dv = v - mean;
    float var = blockSum512(gid == 0 ? dv * dv : 0.f, red) * (1.0f / DD);
    if (gid == 0)
        g_x[bi * DD + d] = dv * rsqrtf(var + 1e-5f) * lng[d] + lnb[d];
}

// ---------------- FFN residual + LN ----------------
__global__ __launch_bounds__(128) void add_ln(
    const float* __restrict__ lng, const float* __restrict__ lnb) {
    __shared__ float red[128];
    const int bi = blockIdx.x;
    const int tid = threadIdx.x;
    float v = g_x[bi * DD + tid] + g_y[bi * DD + tid];
    float mean = blockSum128(v, red) * (1.0f / DD);
    float dv = v - mean;
    float var = blockSum128(dv * dv, red) * (1.0f / DD);
    g_x[bi * DD + tid] = dv * rsqrtf(var + 1e-5f) * lng[tid] + lnb[tid];
}

// ---------------- launcher ----------------
extern "C" void kernel_launch(void* const* d_in, const int* in_sizes, int n_in,
                              void* d_out, int out_size) {
    const int* ids = (const int*)d_in[0];
    const float* embw = (const float*)d_in[1];
    const float* pos = (const float*)d_in[2];
    const float* pW1 = (const float*)d_in[3];
    const float* pb1 = (const float*)d_in[4];
    const float* pW2 = (const float*)d_in[5];
    const float* pb2 = (const float*)d_in[6];
    const float* pW3 = (const float*)d_in[7];
    const float* pb3 = (const float*)d_in[8];
    const float* ln1g = (const float*)d_in[9];
    const float* ln1b = (const float*)d_in[10];
    const float* fW1 = (const float*)d_in[11];
    const float* fb1 = (const float*)d_in[12];
    const float* fW2 = (const float*)d_in[13];
    const float* fb2 = (const float*)d_in[14];
    const float* ln2g = (const float*)d_in[15];
    const float* ln2b = (const float*)d_in[16];
    const float* headW = (const float*)d_in[17];
    const float* headb = (const float*)d_in[18];
    float* out = (float*)d_out;

    cudaFuncSetAttribute(pair_mma, cudaFuncAttributeMaxDynamicSharedMemorySize,
                         PM_SMEM_BYTES);
    cudaFuncSetAttribute(head_mma, cudaFuncAttributeMaxDynamicSharedMemorySize,
                         HD_SMEM_BYTES);
    cudaFuncSetAttribute(gemm_mma64<0>, cudaFuncAttributeMaxDynamicSharedMemorySize,
                         GM_SMEM_BYTES);
    cudaFuncSetAttribute(gemm_mma64<1>, cudaFuncAttributeMaxDynamicSharedMemorySize,
                         GM_SMEM_BYTES);

    float *xp, *ap, *cp, *hp, *yp;
    cudaGetSymbolAddress((void**)&xp, g_x);
    cudaGetSymbolAddress((void**)&ap, g_a);
    cudaGetSymbolAddress((void**)&cp, g_c);
    cudaGetSymbolAddress((void**)&hp, g_h);
    cudaGetSymbolAddress((void**)&yp, g_y);
    __half *w2hp, *w3hp;
    cudaGetSymbolAddress((void**)&w2hp, g_w2h);
    cudaGetSymbolAddress((void**)&w3hp, g_w3h);

    embed_kernel<<<(BB * NN * DD + 255) / 256, 256>>>(ids, embw, pos);
    convert_w<<<(LL * 256 * 128 + LL * 128 * 128 + 255) / 256, 256>>>(pW2, pW3);

    for (int l = 0; l < LL; l++) {
        const float* W1l = pW1 + (size_t)l * 256 * 256;
        gemm_mma64<0><<<dim3(4, 12), 256, GM_SMEM_BYTES>>>(
            xp, 128, W1l, W1l + 128 * 256, 256, 256,
            pb1 + l * 256, nullptr, ap, cp, 256, 128);
        pair_mma<<<NTILES_MMA, 256, PM_SMEM_BYTES>>>(
            w2hp + (size_t)l * 256 * 128, pb2 + l * 128,
            w3hp + (size_t)l * 128 * 128, pb3 + l * 128);
        pair_reduce_ln<<<BB * NN, 512>>>(ln1g + l * 128, ln1b + l * 128);
        gemm_mma64<1><<<dim3(4, 12), 256, GM_SMEM_BYTES>>>(
            xp, 128, fW1 + (size_t)l * 128 * 512, nullptr, 1 << 30, 512,
            fb1 + l * 512, nullptr, hp, nullptr, 512, 128);
        gemm_mma64<0><<<dim3(1, 12), 256, GM_SMEM_BYTES>>>(
            hp, 512, fW2 + (size_t)l * 512 * 128, nullptr, 1 << 30, 128,
            fb2 + l * 128, nullptr, yp, nullptr, 128, 512);
        add_ln<<<BB * NN, 128>>>(ln2g + l * 128, ln2b + l * 128);
    }

    head_mma<<<dim3(VV / 128, 768 / 128), 256, HD_SMEM_BYTES>>>(headW, headb, out);
}

// round 9
// speedup vs baseline: 1.7257x; 1.1893x over previous
#include <cuda_runtime.h>
#include <cuda_fp16.h>
#include <math.h>
#include <stdint.h>

// Problem constants
#define BB 2
#define NN 384
#define DD 128
#define VV 8192
#define LL 2
#define NPAIR_B 73920
#define NPAIR_T 147840
#define PT 128
#define NTILES_MMA 1155      // 147840 / 128

// ---------------- scratch ----------------
__device__ float g_x[BB * NN * DD];
__device__ float g_a[BB * NN * 256];
__device__ float g_c[BB * NN * 256];
__device__ float g_h[BB * NN * 512];
__device__ float g_y[BB * NN * DD];
__device__ __half g_p[(size_t)BB * NN * NN * DD];   // pair vectors, fp16
__device__ float g_s[BB * NN * NN];
__device__ __half g_w2h[LL * 256 * 128];
__device__ __half g_w3h[LL * 128 * 128];

// tanh-form gelu using HW MUFU.TANH: 4 fma/mul + 1 MUFU
__device__ __forceinline__ float gelu_fast(float x) {
    float x2 = x * x;
    float inner = fmaf(0.0356774081f, x2, 0.7978845608f);
    float u = x * inner;
    float t;
    asm("tanh.approx.f32 %0, %1;" : "=f"(t) : "f"(u));
    float hx = 0.5f * x;
    return fmaf(hx, t, hx);
}

__device__ __forceinline__ void ldsm4(uint32_t* r, uint32_t addr) {
    asm volatile("ldmatrix.sync.aligned.m8n8.x4.shared.b16 {%0,%1,%2,%3}, [%4];"
                 : "=r"(r[0]), "=r"(r[1]), "=r"(r[2]), "=r"(r[3]) : "r"(addr));
}
__device__ __forceinline__ void ldsm4t(uint32_t* r, uint32_t addr) {
    asm volatile("ldmatrix.sync.aligned.m8n8.x4.trans.shared.b16 {%0,%1,%2,%3}, [%4];"
                 : "=r"(r[0]), "=r"(r[1]), "=r"(r[2]), "=r"(r[3]) : "r"(addr));
}
__device__ __forceinline__ void mma_f16(float c[4], const uint32_t a[4],
                                        uint32_t b0, uint32_t b1) {
    asm volatile(
        "mma.sync.aligned.m16n8k16.row.col.f32.f16.f16.f32 "
        "{%0,%1,%2,%3}, {%4,%5,%6,%7}, {%8,%9}, {%0,%1,%2,%3};"
        : "+f"(c[0]), "+f"(c[1]), "+f"(c[2]), "+f"(c[3])
        : "r"(a[0]), "r"(a[1]), "r"(a[2]), "r"(a[3]), "r"(b0), "r"(b1));
}
__device__ __forceinline__ void cpa16(uint32_t daddr, const void* g) {
    asm volatile("cp.async.cg.shared.global [%0], [%1], 16;" :: "r"(daddr), "l"(g));
}
#define CP_COMMIT asm volatile("cp.async.commit_group;")
#define CP_WAIT0 asm volatile("cp.async.wait_group 0;")

// ---------------- weight pre-convert ----------------
__global__ void convert_w(const float* __restrict__ pW2, const float* __restrict__ pW3) {
    int t = blockIdx.x * 256 + threadIdx.x;
    const int n2 = LL * 256 * 128;
    const int n3 = LL * 128 * 128;
    if (t < n2) g_w2h[t] = __float2half(pW2[t]);
    int t3 = t - n2;
    if (t3 >= 0 && t3 < n3) g_w3h[t3] = __float2half(pW3[t3]);
}

// ---------------- embedding ----------------
__global__ void embed_kernel(const int* __restrict__ ids,
                             const float* __restrict__ emb,
                             const float* __restrict__ pos) {
    int t = blockIdx.x * blockDim.x + threadIdx.x;
    if (t >= BB * NN * DD) return;
    int d = t & (DD - 1);
    int bn = t >> 7;
    int n = bn % NN;
    g_x[t] = emb[ids[bn] * DD + d] + pos[n * DD + d];
}

// ================= generic fp16-mma GEMM, 64(M)x128(N) tiles ================
#define SBW 136
#define SPF 132
#define GM_OX 0
#define GM_OW 17408
#define GM_OB 52224
#define GM_SMEM_BYTES 52736

template <int ACT>
__global__ __launch_bounds__(256, 2) void gemm_mma64(
    const float* __restrict__ A, int ldA,
    const float* __restrict__ Wa, const float* __restrict__ Wb, int nsplit, int ldW,
    const float* __restrict__ ba, const float* __restrict__ bb,
    float* __restrict__ Ca, float* __restrict__ Cb, int ldC, int K) {
    extern __shared__ char smc[];
    __half* Xh = (__half*)(smc + GM_OX);
    __half* Wh = (__half*)(smc + GM_OW);
    float* biass = (float*)(smc + GM_OB);
    float* Pf = (float*)smc;

    const int tid = threadIdx.x;
    const int lane = tid & 31;
    const int warp = tid >> 5;
    const int wm = warp >> 2;
    const int wn = warp & 3;
    const int lr = lane >> 2;
    const int lc = lane & 3;
    const int lrow = (lane & 7) + ((lane >> 3) & 1) * 8;
    const int lcol = (lane >> 4) * 8;

    const int n0 = blockIdx.x * 128;
    const int m0 = blockIdx.y * 64;

    const float* Wsrc;
    const float* bsrc;
    float* Cdst;
    if (n0 < nsplit) {
        Wsrc = Wa + n0;
        bsrc = ba ? ba + n0 : nullptr;
        Cdst = Ca + n0;
    } else {
        int nn = n0 - nsplit;
        Wsrc = Wb + nn;
        bsrc = bb ? bb + nn : nullptr;
        Cdst = Cb + nn;
    }

    const uint32_t sb = (uint32_t)__cvta_generic_to_shared(smc);
    const uint32_t x_lane = sb + GM_OX + (uint32_t)(lrow * SBW + lcol) * 2;
    const uint32_t w_lane = sb + GM_OW + (uint32_t)(lrow * SBW + lcol) * 2;

    if (tid < 128) biass[tid] = bsrc ? bsrc[tid] : 0.f;

    float acc[2][4][4] = {};
    uint32_t af[2][4];
    uint32_t bf[4];

    const int nkc = K >> 7;
    for (int kc = 0; kc < nkc; kc++) {
        const int k0 = kc << 7;
        for (int e = tid; e < 64 * 32; e += 256) {
            int r = e >> 5, c4 = e & 31;
            const float4 v = *(const float4*)&A[(size_t)(m0 + r) * ldA + k0 + c4 * 4];
            __half2* d = (__half2*)(Xh + r * SBW + c4 * 4);
            d[0] = __floats2half2_rn(v.x, v.y);
            d[1] = __floats2half2_rn(v.z, v.w);
        }
        for (int e = tid; e < 128 * 32; e += 256) {
            int k = e >> 5, n4 = e & 31;
            const float4 v = *(const float4*)&Wsrc[(size_t)(k0 + k) * ldW + n4 * 4];
            __half2* d = (__half2*)(Wh + k * SBW + n4 * 4);
            d[0] = __floats2half2_rn(v.x, v.y);
            d[1] = __floats2half2_rn(v.z, v.w);
        }
        __syncthreads();
#pragma unroll
        for (int ks = 0; ks < 8; ks++) {
            const int kb = ks * 16;
            ldsm4(af[0], x_lane + (uint32_t)((wm * 32) * SBW + kb) * 2);
            ldsm4(af[1], x_lane + (uint32_t)((wm * 32 + 16) * SBW + kb) * 2);
#pragma unroll
            for (int bt = 0; bt < 2; bt++) {
                ldsm4t(bf, w_lane + (uint32_t)(kb * SBW + wn * 32 + bt * 16) * 2);
                mma_f16(acc[0][2 * bt], af[0], bf[0], bf[1]);
                mma_f16(acc[1][2 * bt], af[1], bf[0], bf[1]);
                mma_f16(acc[0][2 * bt + 1], af[0], bf[2], bf[3]);
                mma_f16(acc[1][2 * bt + 1], af[1], bf[2], bf[3]);
            }
        }
        __syncthreads();
    }

#pragma unroll
    for (int mt = 0; mt < 2; mt++) {
        int r0 = wm * 32 + mt * 16 + lr;
#pragma unroll
        for (int nt = 0; nt < 4; nt++) {
            int cb = wn * 32 + nt * 8 + 2 * lc;
            float o0 = acc[mt][nt][0] + biass[cb];
            float o1 = acc[mt][nt][1] + biass[cb + 1];
            float o2 = acc[mt][nt][2] + biass[cb];
            float o3 = acc[mt][nt][3] + biass[cb + 1];
            if (ACT == 1) {
                o0 = gelu_fast(o0); o1 = gelu_fast(o1);
                o2 = gelu_fast(o2); o3 = gelu_fast(o3);
            }
            *(float2*)(Pf + r0 * SPF + cb) = make_float2(o0, o1);
            *(float2*)(Pf + (r0 + 8) * SPF + cb) = make_float2(o2, o3);
        }
    }
    __syncthreads();

    {
        int r = tid >> 2, q = tid & 3;
        const float* src = Pf + r * SPF + q * 32;
        float* dst = Cdst + (size_t)(m0 + r) * ldC + q * 32;
#pragma unroll
        for (int u = 0; u < 32; u += 4)
            *(float4*)(dst + u) = *(const float4*)(src + u);
    }
}

// ---------------- pair kernel: chunked, cp.async dbl-buffered W, fp16 mma ---
#define SA 72
#define SH 136
#define OWB0 0
#define OWB1 17408
#define OH1 34816
#define OH2 53248
#define OB2 88064
#define OB3 88576
#define ORA 89088
#define ORC 89600
#define OPO 90112
#define ONW 90624
#define PM_SMEM_BYTES 91648

__global__ __launch_bounds__(256, 2) void pair_mma(
    const __half* __restrict__ W2h, const float* __restrict__ b2,
    const __half* __restrict__ W3h, const float* __restrict__ b3) {
    extern __shared__ char smc[];
    __half* H1s = (__half*)(smc + OH1);
    __half* H2s = (__half*)(smc + OH2);
    float* b2s = (float*)(smc + OB2);
    float* b3s = (float*)(smc + OB3);
    int* rowA = (int*)(smc + ORA);
    int* rowC = (int*)(smc + ORC);
    int* poff = (int*)(smc + OPO);
    float* normw = (float*)(smc + ONW);   // [128][2] per-row partial sq-sums

    const int tid = threadIdx.x;
    const int lane = tid & 31;
    const int warp = tid >> 5;
    const int wm = warp >> 1;
    const int wn = warp & 1;
    const int lr = lane >> 2;
    const int lc = lane & 3;
    const int lrow = (lane & 7) + ((lane >> 3) & 1) * 8;
    const int lcol = (lane >> 4) * 8;

    const uint32_t sb = (uint32_t)__cvta_generic_to_shared(smc);
    const uint32_t h1_lane = sb + OH1 + (uint32_t)(lrow * SA + lcol) * 2;
    const uint32_t h2_lane = sb + OH2 + (uint32_t)(lrow * SH + lcol) * 2;
    const uint32_t w_lane0 = sb + OWB0 + (uint32_t)(lrow * SBW + lcol) * 2;
    const uint32_t w_lane1 = sb + OWB1 + (uint32_t)(lrow * SBW + lcol) * 2;

    {
        const __half* src = W2h;
        uint32_t dbase = sb + OWB0;
#pragma unroll
        for (int e = tid; e < 1024; e += 256) {
            int row = e >> 4, seg = e & 15;
            cpa16(dbase + row * (SBW * 2) + seg * 16, src + row * 128 + seg * 8);
        }
        CP_COMMIT;
    }

    if (tid < 128) {
        b2s[tid] = b2[tid];
        b3s[tid] = b3[tid];
        int g = blockIdx.x * PT + tid;
        int b = (g >= NPAIR_B) ? 1 : 0;
        int idx = g - b * NPAIR_B;
        int i = (int)((sqrtf(8.0f * (float)idx + 1.0f) - 1.0f) * 0.5f);
        while ((i + 1) * (i + 2) / 2 <= idx) ++i;
        while (i * (i + 1) / 2 > idx) --i;
        int j = idx - i * (i + 1) / 2;
        rowA[tid] = b * NN + i;
        rowC[tid] = b * NN + j;
        poff[tid] = (b * NN + i) * NN + j;
    }
    __syncthreads();

#pragma unroll
    for (int e = tid; e < 128 * 16; e += 256) {
        int r = e >> 4, c4 = e & 15;
        const float4 av = *(const float4*)&g_a[rowA[r] * 256 + c4 * 4];
        const float4 cv = *(const float4*)&g_c[rowC[r] * 256 + c4 * 4];
        __half2* d = (__half2*)(H1s + r * SA + c4 * 4);
        d[0] = __floats2half2_rn(gelu_fast(av.x + cv.x), gelu_fast(av.y + cv.y));
        d[1] = __floats2half2_rn(gelu_fast(av.z + cv.z), gelu_fast(av.w + cv.w));
    }
    CP_WAIT0;
    __syncthreads();

    float acc[2][8][4] = {};
    uint32_t af[2][4];
    uint32_t bf[4];

    for (int kc = 0; kc < 4; kc++) {
        if (kc < 3) {
            const __half* src = W2h + (kc + 1) * 64 * 128;
            uint32_t dbase = sb + (((kc + 1) & 1) ? OWB1 : OWB0);
#pragma unroll
            for (int e = tid; e < 1024; e += 256) {
                int row = e >> 4, seg = e & 15;
                cpa16(dbase + row * (SBW * 2) + seg * 16, src + row * 128 + seg * 8);
            }
            CP_COMMIT;
        }
        const uint32_t wl = (kc & 1) ? w_lane1 : w_lane0;
#pragma unroll
        for (int ks = 0; ks < 4; ks++) {
            const int kb = ks * 16;
            ldsm4(af[0], h1_lane + (uint32_t)((wm * 32) * SA + kb) * 2);
            ldsm4(af[1], h1_lane + (uint32_t)((wm * 32 + 16) * SA + kb) * 2);
#pragma unroll
            for (int bt = 0; bt < 4; bt++) {
                ldsm4t(bf, wl + (uint32_t)(kb * SBW + wn * 64 + bt * 16) * 2);
                mma_f16(acc[0][2 * bt], af[0], bf[0], bf[1]);
                mma_f16(acc[1][2 * bt], af[1], bf[0], bf[1]);
                mma_f16(acc[0][2 * bt + 1], af[0], bf[2], bf[3]);
                mma_f16(acc[1][2 * bt + 1], af[1], bf[2], bf[3]);
            }
        }
        __syncthreads();
        if (kc < 3) {
            const int k0 = (kc + 1) * 64;
#pragma unroll
            for (int e = tid; e < 128 * 16; e += 256) {
                int r = e >> 4, c4 = e & 15;
                const float4 av = *(const float4*)&g_a[rowA[r] * 256 + k0 + c4 * 4];
                const float4 cv = *(const float4*)&g_c[rowC[r] * 256 + k0 + c4 * 4];
                __half2* d = (__half2*)(H1s + r * SA + c4 * 4);
                d[0] = __floats2half2_rn(gelu_fast(av.x + cv.x), gelu_fast(av.y + cv.y));
                d[1] = __floats2half2_rn(gelu_fast(av.z + cv.z), gelu_fast(av.w + cv.w));
            }
            CP_WAIT0;
            __syncthreads();
        }
    }

#pragma unroll
    for (int ch = 0; ch < 2; ch++) {
        const __half* src = W3h + ch * 64 * 128;
        uint32_t dbase = sb + (ch ? OWB1 : OWB0);
#pragma unroll
        for (int e = tid; e < 1024; e += 256) {
            int row = e >> 4, seg = e & 15;
            cpa16(dbase + row * (SBW * 2) + seg * 16, src + row * 128 + seg * 8);
        }
        CP_COMMIT;
    }

#pragma unroll
    for (int mt = 0; mt < 2; mt++) {
        int r0 = wm * 32 + mt * 16 + lr;
#pragma unroll
        for (int nt = 0; nt < 8; nt++) {
            int cb = wn * 64 + nt * 8 + 2 * lc;
            float bx = b2s[cb], by = b2s[cb + 1];
            *(__half2*)(H2s + r0 * SH + cb) =
                __floats2half2_rn(gelu_fast(acc[mt][nt][0] + bx), gelu_fast(acc[mt][nt][1] + by));
            *(__half2*)(H2s + (r0 + 8) * SH + cb) =
                __floats2half2_rn(gelu_fast(acc[mt][nt][2] + bx), gelu_fast(acc[mt][nt][3] + by));
        }
    }
    CP_WAIT0;
    __syncthreads();

    float acc2[2][8][4] = {};
#pragma unroll
    for (int ks = 0; ks < 8; ks++) {
        const int kbg = ks * 16;
        const uint32_t wl = (kbg & 64) ? w_lane1 : w_lane0;
        const int kb = kbg & 63;
        ldsm4(af[0], h2_lane + (uint32_t)((wm * 32) * SH + kbg) * 2);
        ldsm4(af[1], h2_lane + (uint32_t)((wm * 32 + 16) * SH + kbg) * 2);
#pragma unroll
        for (int bt = 0; bt < 4; bt++) {
            ldsm4t(bf, wl + (uint32_t)(kb * SBW + wn * 64 + bt * 16) * 2);
            mma_f16(acc2[0][2 * bt], af[0], bf[0], bf[1]);
            mma_f16(acc2[1][2 * bt], af[1], bf[0], bf[1]);
            mma_f16(acc2[0][2 * bt + 1], af[0], bf[2], bf[3]);
            mma_f16(acc2[1][2 * bt + 1], af[1], bf[2], bf[3]);
        }
    }
    __syncthreads();   // H2s reads done -> safe to overwrite with fp16 P

    // epilogue 2: +b3, fp16 into H2s region, norms from fp32 registers
#pragma unroll
    for (int mt = 0; mt < 2; mt++) {
        int r0 = wm * 32 + mt * 16 + lr;
        float n0s = 0.f, n1s = 0.f;
#pragma unroll
        for (int nt = 0; nt < 8; nt++) {
            int cb = wn * 64 + nt * 8 + 2 * lc;
            float bx = b3s[cb], by = b3s[cb + 1];
            float o0 = acc2[mt][nt][0] + bx, o1 = acc2[mt][nt][1] + by;
            float o2 = acc2[mt][nt][2] + bx, o3 = acc2[mt][nt][3] + by;
            n0s += o0 * o0 + o1 * o1;
            n1s += o2 * o2 + o3 * o3;
            *(__half2*)(H2s + r0 * SH + cb) = __floats2half2_rn(o0, o1);
            *(__half2*)(H2s + (r0 + 8) * SH + cb) = __floats2half2_rn(o2, o3);
        }
        n0s += __shfl_xor_sync(0xffffffffu, n0s, 1);
        n0s += __shfl_xor_sync(0xffffffffu, n0s, 2);
        n1s += __shfl_xor_sync(0xffffffffu, n1s, 1);
        n1s += __shfl_xor_sync(0xffffffffu, n1s, 2);
        if (lc == 0) {
            normw[r0 * 2 + wn] = n0s;
            normw[(r0 + 8) * 2 + wn] = n1s;
        }
    }
    __syncthreads();

    // writeout: fp16 rows, 2 threads per pair-row (128 B = 8 uint4 each)
    {
        int r = tid >> 1, hf = tid & 1;
        const uint4* src = (const uint4*)(smc + OH2 + r * (SH * 2) + hf * 128);
        uint4* dst = (uint4*)(g_p + (size_t)poff[r] * DD + hf * 64);
#pragma unroll
        for (int u = 0; u < 8; u++) dst[u] = src[u];
    }
    if (tid < 128) {
        float ss = normw[tid * 2] + normw[tid * 2 + 1];
        g_s[poff[tid]] = sqrtf(fmaxf(ss, 1e-30f));
    }
}

// ---------------- head: fp16 mma, 128x128 tiles ----------------
#define OHX 0
#define OHW 34816
#define OHB 69632
#define HD_SMEM_BYTES 70144

__global__ __launch_bounds__(256) void head_mma(
    const float* __restrict__ headW, const float* __restrict__ headb,
    float* __restrict__ out) {
    extern __shared__ char smc[];
    __half* Xh = (__half*)(smc + OHX);
    __half* Wh = (__half*)(smc + OHW);
    float* biass = (float*)(smc + OHB);
    float* Pf = (float*)smc;

    const int tid = threadIdx.x;
    const int lane = tid & 31;
    const int warp = tid >> 5;
    const int wm = warp >> 1;
    const int wn = warp & 1;
    const int lr = lane >> 2;
    const int lc = lane & 3;
    const int lrow = (lane & 7) + ((lane >> 3) & 1) * 8;
    const int lcol = (lane >> 4) * 8;

    const int n0 = blockIdx.x * 128;
    const int m0 = blockIdx.y * 128;

    const uint32_t sb = (uint32_t)__cvta_generic_to_shared(smc);
    const uint32_t x_lane = sb + OHX + (uint32_t)(lrow * SBW + lcol) * 2;
    const uint32_t w_lane = sb + OHW + (uint32_t)(lrow * SBW + lcol) * 2;

    for (int e = tid; e < 128 * 32; e += 256) {
        int r = e >> 5, c4 = e & 31;
        const float4 v = *(const float4*)&g_x[(m0 + r) * DD + c4 * 4];
        __half2* d = (__half2*)(Xh + r * SBW + c4 * 4);
        d[0] = __floats2half2_rn(v.x, v.y);
        d[1] = __floats2half2_rn(v.z, v.w);
    }
    for (int e = tid; e < 128 * 32; e += 256) {
        int k = e >> 5, n4 = e & 31;
        const float4 v = *(const float4*)&headW[(size_t)k * VV + n0 + n4 * 4];
        __half2* d = (__half2*)(Wh + k * SBW + n4 * 4);
        d[0] = __floats2half2_rn(v.x, v.y);
        d[1] = __floats2half2_rn(v.z, v.w);
    }
    if (tid < 128) biass[tid] = headb[n0 + tid];
    __syncthreads();

    float acc[2][8][4] = {};
    uint32_t af[2][4];
    uint32_t bf[4];
#pragma unroll
    for (int ks = 0; ks < 8; ks++) {
        const int kb = ks * 16;
        ldsm4(af[0], x_lane + (uint32_t)((wm * 32) * SBW + kb) * 2);
        ldsm4(af[1], x_lane + (uint32_t)((wm * 32 + 16) * SBW + kb) * 2);
#pragma unroll
        for (int bt = 0; bt < 4; bt++) {
            ldsm4t(bf, w_lane + (uint32_t)(kb * SBW + wn * 64 + bt * 16) * 2);
            mma_f16(acc[0][2 * bt], af[0], bf[0], bf[1]);
            mma_f16(acc[1][2 * bt], af[1], bf[0], bf[1]);
            mma_f16(acc[0][2 * bt + 1], af[0], bf[2], bf[3]);
            mma_f16(acc[1][2 * bt + 1], af[1], bf[2], bf[3]);
        }
    }
    __syncthreads();

#pragma unroll
    for (int mt = 0; mt < 2; mt++) {
        int r0 = wm * 32 + mt * 16 + lr;
#pragma unroll
        for (int nt = 0; nt < 8; nt++) {
            int cb = wn * 64 + nt * 8 + 2 * lc;
            float bx = biass[cb], by = biass[cb + 1];
            *(float2*)(Pf + r0 * SPF + cb) =
                make_float2(acc[mt][nt][0] + bx, acc[mt][nt][1] + by);
            *(float2*)(Pf + (r0 + 8) * SPF + cb) =
                make_float2(acc[mt][nt][2] + bx, acc[mt][nt][3] + by);
        }
    }
    __syncthreads();

    {
        int r = tid >> 1, hf = tid & 1;
        const float* src = Pf + r * SPF + hf * 64;
        float* dst = out + (size_t)(m0 + r) * VV + n0 + hf * 64;
#pragma unroll
        for (int u = 0; u < 64; u += 4)
            *(float4*)(dst + u) = *(const float4*)(src + u);
    }
}

// ---------------- block reductions ----------------
__device__ __forceinline__ float blockSum512(float v, float* red) {
    int tid = threadIdx.x;
    red[tid] = v;
    __syncthreads();
    for (int s = 256; s; s >>= 1) {
        if (tid < s) red[tid] += red[tid + s];
        __syncthreads();
    }
    float r = red[0];
    __syncthreads();
    return r;
}
__device__ __forceinline__ float blockMax512(float v, float* red) {
    int tid = threadIdx.x;
    red[tid] = v;
    __syncthreads();
    for (int s = 256; s; s >>= 1) {
        if (tid < s) red[tid] = fmaxf(red[tid], red[tid + s]);
        __syncthreads();
    }
    float r = red[0];
    __syncthreads();
    return r;
}
__device__ __forceinline__ float blockSum128(float v, float* red) {
    int tid = threadIdx.x;
    red[tid] = v;
    __syncthreads();
    for (int s = 64; s; s >>= 1) {
        if (tid < s) red[tid] += red[tid + s];
        __syncthreads();
    }
    float r = red[0];
    __syncthreads();
    return r;
}

// ---------------- phase B: softmax + weighted sum + residual + LN ----------
// 512 threads: 8 j-groups x 64 col-pair lanes, half2 loads of g_p
__global__ __launch_bounds__(512) void pair_reduce_ln(
    const float* __restrict__ lng, const float* __restrict__ lnb) {
    __shared__ float red[512];
    __shared__ float ws[NN];
    __shared__ float accbuf[8][128];
    const int bi = blockIdx.x;
    const int i = bi % NN;
    const int tid = threadIdx.x;
    const int gid = tid >> 6;
    const int c2 = tid & 63;
    const int np = i + 1;
    const float* srow = g_s + (size_t)bi * NN;

    float lm = -1e30f;
    for (int j = tid; j < np; j += 512) lm = fmaxf(lm, srow[j]);
    float m = blockMax512(lm, red);

    float dsum = 0.f;
    for (int j = tid; j < np; j += 512) {
        float w = expf(srow[j] - m);
        ws[j] = w;
        dsum += w;
    }
    float den = blockSum512(dsum, red);

    const __half2* prow = (const __half2*)(g_p + (size_t)bi * NN * DD);
    float ax = 0.f, ay = 0.f;
#pragma unroll 2
    for (int j = gid; j < np; j += 8) {
        float w = ws[j];
        float2 pf = __half22float2(prow[j * 64 + c2]);
        ax = fmaf(w, pf.x, ax);
        ay = fmaf(w, pf.y, ay);
    }
    accbuf[gid][c2 * 2] = ax;
    accbuf[gid][c2 * 2 + 1] = ay;
    __syncthreads();

    float v = 0.f;
    if (tid < 128) {
        float s = 0.f;
#pragma unroll
        for (int g = 0; g < 8; g++) s += accbuf[g][tid];
        v = g_x[bi * DD + tid] + s / den;
    }
    float mean = blockSum512(tid < 128 ? v : 0.f, red) * (1.0f / DD);
    float dv = v - mean;
    float var = blockSum512(tid < 128 ? dv * dv : 0.f, red) * (1.0f / DD);
    if (tid < 128)
        g_x[bi * DD + tid] = dv * rsqrtf(var + 1e-5f) * lng[tid] + lnb[tid];
}

// ---------------- FFN residual + LN ----------------
__global__ __launch_bounds__(128) void add_ln(
    const float* __restrict__ lng, const float* __restrict__ lnb) {
    __shared__ float red[128];
    const int bi = blockIdx.x;
    const int tid = threadIdx.x;
    float v = g_x[bi * DD + tid] + g_y[bi * DD + tid];
    float mean = blockSum128(v, red) * (1.0f / DD);
    float dv = v - mean;
    float var = blockSum128(dv * dv, red) * (1.0f / DD);
    g_x[bi * DD + tid] = dv * rsqrtf(var + 1e-5f) * lng[tid] + lnb[tid];
}

// ---------------- launcher ----------------
extern "C" void kernel_launch(void* const* d_in, const int* in_sizes, int n_in,
                              void* d_out, int out_size) {
    const int* ids = (const int*)d_in[0];
    const float* embw = (const float*)d_in[1];
    const float* pos = (const float*)d_in[2];
    const float* pW1 = (const float*)d_in[3];
    const float* pb1 = (const float*)d_in[4];
    const float* pW2 = (const float*)d_in[5];
    const float* pb2 = (const float*)d_in[6];
    const float* pW3 = (const float*)d_in[7];
    const float* pb3 = (const float*)d_in[8];
    const float* ln1g = (const float*)d_in[9];
    const float* ln1b = (const float*)d_in[10];
    const float* fW1 = (const float*)d_in[11];
    const float* fb1 = (const float*)d_in[12];
    const float* fW2 = (const float*)d_in[13];
    const float* fb2 = (const float*)d_in[14];
    const float* ln2g = (const float*)d_in[15];
    const float* ln2b = (const float*)d_in[16];
    const float* headW = (const float*)d_in[17];
    const float* headb = (const float*)d_in[18];
    float* out = (float*)d_out;

    cudaFuncSetAttribute(pair_mma, cudaFuncAttributeMaxDynamicSharedMemorySize,
                         PM_SMEM_BYTES);
    cudaFuncSetAttribute(head_mma, cudaFuncAttributeMaxDynamicSharedMemorySize,
                         HD_SMEM_BYTES);
    cudaFuncSetAttribute(gemm_mma64<0>, cudaFuncAttributeMaxDynamicSharedMemorySize,
                         GM_SMEM_BYTES);
    cudaFuncSetAttribute(gemm_mma64<1>, cudaFuncAttributeMaxDynamicSharedMemorySize,
                         GM_SMEM_BYTES);

    float *xp, *ap, *cp, *hp, *yp;
    cudaGetSymbolAddress((void**)&xp, g_x);
    cudaGetSymbolAddress((void**)&ap, g_a);
    cudaGetSymbolAddress((void**)&cp, g_c);
    cudaGetSymbolAddress((void**)&hp, g_h);
    cudaGetSymbolAddress((void**)&yp, g_y);
    __half *w2hp, *w3hp;
    cudaGetSymbolAddress((void**)&w2hp, g_w2h);
    cudaGetSymbolAddress((void**)&w3hp, g_w3h);

    embed_kernel<<<(BB * NN * DD + 255) / 256, 256>>>(ids, embw, pos);
    convert_w<<<(LL * 256 * 128 + LL * 128 * 128 + 255) / 256, 256>>>(pW2, pW3);

    for (int l = 0; l < LL; l++) {
        const float* W1l = pW1 + (size_t)l * 256 * 256;
        gemm_mma64<0><<<dim3(4, 12), 256, GM_SMEM_BYTES>>>(
            xp, 128, W1l, W1l + 128 * 256, 256, 256,
            pb1 + l * 256, nullptr, ap, cp, 256, 128);
        pair_mma<<<NTILES_MMA, 256, PM_SMEM_BYTES>>>(
            w2hp + (size_t)l * 256 * 128, pb2 + l * 128,
            w3hp + (size_t)l * 128 * 128, pb3 + l * 128);
        pair_reduce_ln<<<BB * NN, 512>>>(ln1g + l * 128, ln1b + l * 128);
        gemm_mma64<1><<<dim3(4, 12), 256, GM_SMEM_BYTES>>>(
            xp, 128, fW1 + (size_t)l * 128 * 512, nullptr, 1 << 30, 512,
            fb1 + l * 512, nullptr, hp, nullptr, 512, 128);
        gemm_mma64<0><<<dim3(1, 12), 256, GM_SMEM_BYTES>>>(
            hp, 512, fW2 + (size_t)l * 512 * 128, nullptr, 1 << 30, 128,
            fb2 + l * 128, nullptr, yp, nullptr, 128, 512);
        add_ln<<<BB * NN, 128>>>(ln2g + l * 128, ln2b + l * 128);
    }

    head_mma<<<dim3(VV / 128, 768 / 128), 256, HD_SMEM_BYTES>>>(headW, headb, out);
}